// round 12
// baseline (speedup 1.0000x reference)
#include <cuda_runtime.h>
#include <cuda_bf16.h>
#include <math.h>
#include <stdint.h>

#define B 2
#define YC 256
#define SC 128
#define YH 64
#define NQ 4096        /* 64*64  */
#define SHW 128
#define NS 16384       /* 128*128 */
#define HEADS 4
#define DH 32
#define EPS 1e-5f

// ---------------- scratch (device globals; no allocations allowed) -------------
__device__ float g_ype[B * YC * NQ];
__device__ float g_spe[B * SC * NS];
__device__ float g_big[B * SC * NS];
__device__ float g_q[B * SC * NQ];
__device__ float g_v[B * SC * NQ];
__device__ float g_att[B * SC * NQ];
__device__ float g_sum0[B * SC], g_sq0[B * SC];
__device__ float g_sum1[B * SC], g_sq1[B * SC];
__device__ float g_sum2[B * SC], g_sq2[B * SC];
__device__ float g_lsum[B], g_lsq[B];
__device__ float g_rate[192];
__device__ float g_w2g[YC * 4 * 4 * SC];
__device__ float g_w2p[SC * 4 * 4 * SC];
__device__ uint32_t g_w1yh[YC * 9 / 2 * SC], g_w1yl[YC * 9 / 2 * SC];
__device__ uint32_t g_w1sh[SC * 9 / 2 * SC], g_w1sl[SC * 9 / 2 * SC];

__device__ __forceinline__ int refl(int i, int n) {
    return i < 0 ? -i : (i >= n ? 2 * n - 2 - i : i);
}

// ---------------- mma helpers ---------------------------------------------------
__device__ __forceinline__ void mma_bf16(float& d0, float& d1, float& d2, float& d3,
                                         uint32_t a0, uint32_t a1, uint32_t a2, uint32_t a3,
                                         uint32_t b0, uint32_t b1) {
    asm volatile("mma.sync.aligned.m16n8k16.row.col.f32.bf16.bf16.f32 "
                 "{%0,%1,%2,%3}, {%4,%5,%6,%7}, {%8,%9}, {%0,%1,%2,%3};"
                 : "+f"(d0), "+f"(d1), "+f"(d2), "+f"(d3)
                 : "r"(a0), "r"(a1), "r"(a2), "r"(a3), "r"(b0), "r"(b1));
}
__device__ __forceinline__ void mma_tf32(float& d0, float& d1, float& d2, float& d3,
                                         uint32_t a0, uint32_t a1, uint32_t a2, uint32_t a3,
                                         uint32_t b0, uint32_t b1) {
    asm volatile("mma.sync.aligned.m16n8k8.row.col.f32.tf32.tf32.f32 "
                 "{%0,%1,%2,%3}, {%4,%5,%6,%7}, {%8,%9}, {%0,%1,%2,%3};"
                 : "+f"(d0), "+f"(d1), "+f"(d2), "+f"(d3)
                 : "r"(a0), "r"(a1), "r"(a2), "r"(a3), "r"(b0), "r"(b1));
}
__device__ __forceinline__ uint32_t f2tf32(float f) {
    uint32_t u; asm("cvt.rna.tf32.f32 %0, %1;" : "=r"(u) : "f"(f)); return u;
}
__device__ __forceinline__ uint32_t packbf(float f0, float f1) {
    __nv_bfloat162 v = __floats2bfloat162_rn(f0, f1);
    return *reinterpret_cast<uint32_t*>(&v);
}
__device__ __forceinline__ float bfhi(float f) {
    return __bfloat162float(__float2bfloat16_rn(f));
}

// ---------------- rate table ---------------------------------------------------
__global__ void rate_init_kernel() {
    int t = threadIdx.x;
    if (t < 128) {
        double d = (double)t / 128.0;
        g_rate[t] = (float)exp(-d * 9.210340371976184);
    } else if (t < 192) {
        double d = (double)(t - 128) / 64.0;
        g_rate[t] = (float)exp(-d * 9.210340371976184);
    }
}

// ---------------- positional encoding ------------------------------------------
__global__ void pe_kernel(const float* __restrict__ x, int outSel, int C, int L, int rateOff) {
    int idx = blockIdx.x * blockDim.x + threadIdx.x;
    int total = B * C * L;
    if (idx >= total) return;
    int l = idx % L;
    int c = (idx / L) % C;
    int half = C >> 1;
    int ch = c < half ? c : c - half;
    float rate = g_rate[rateOff + ch];
    float angf = (float)l * rate;
    double a = (double)angf;
    double k = floor(a * 0.15915494309189535);
    float r = (float)(a - k * 6.283185307179586);
    float pe = (c < half) ? sinf(r) : cosf(r);
    float* o = (outSel == 0) ? g_ype : g_spe;
    o[idx] = x[idx] + pe;
}

// ---------------- sub-filter weight precompute (upsample convs) ----------------
__global__ void w2_precompute_kernel(const float* __restrict__ w, float* __restrict__ w2,
                                     int IC) {
    int t = blockIdx.x * blockDim.x + threadIdx.x;
    if (t >= SC * IC) return;
    int oc = t % SC;
    int ic = t / SC;
    float wv[3][3];
#pragma unroll
    for (int ki = 0; ki < 3; ki++)
#pragma unroll
        for (int kj = 0; kj < 3; kj++)
            wv[ki][kj] = w[((size_t)(oc * IC + ic) * 3 + ki) * 3 + kj];
#pragma unroll
    for (int rp = 0; rp < 2; rp++) {
        float rw[2][3];
#pragma unroll
        for (int kj = 0; kj < 3; kj++) {
            if (rp == 0) { rw[0][kj] = wv[0][kj]; rw[1][kj] = wv[1][kj] + wv[2][kj]; }
            else         { rw[0][kj] = wv[0][kj] + wv[1][kj]; rw[1][kj] = wv[2][kj]; }
        }
#pragma unroll
        for (int cv = 0; cv < 2; cv++) {
#pragma unroll
            for (int dr = 0; dr < 2; dr++) {
                float f0, f1;
                if (cv == 0) { f0 = rw[dr][0]; f1 = rw[dr][1] + rw[dr][2]; }
                else         { f0 = rw[dr][0] + rw[dr][1]; f1 = rw[dr][2]; }
                int v = rp * 2 + cv;
                w2[(((size_t)ic * 4 + v) * 4 + dr * 2 + 0) * SC + oc] = f0;
                w2[(((size_t)ic * 4 + v) * 4 + dr * 2 + 1) * SC + oc] = f1;
            }
        }
    }
}

// ---------------- blue weight repack: packed bf16 k-pairs ----------------------
__global__ void w1_repack_kernel(const float* __restrict__ w, uint32_t* __restrict__ wh,
                                 uint32_t* __restrict__ wl, int IC) {
    int tot = IC * 9 / 2 * SC;
    int t = blockIdx.x * blockDim.x + threadIdx.x;
    if (t >= tot) return;
    int oc = t & 127;
    int kk = t >> 7;
    int k0 = 2 * kk, k1 = 2 * kk + 1;
    float f0 = w[((size_t)oc * IC + k0 / 9) * 9 + k0 % 9];
    float f1 = w[((size_t)oc * IC + k1 / 9) * 9 + k1 % 9];
    float h0 = bfhi(f0), h1 = bfhi(f1);
    wh[t] = packbf(f0, f1);
    wl[t] = packbf(f0 - h0, f1 - h1);
}

// ---------------- blue convs via bf16x3 implicit GEMM (pipelined) --------------
#define KCH 16
__global__ __launch_bounds__(256) void conv_blue_mma_kernel(
    const float* __restrict__ in, const uint32_t* __restrict__ wh,
    const uint32_t* __restrict__ wl, float* __restrict__ outp,
    int IC, int stride, int HI) {
    __shared__ uint32_t sAh[8][72], sAl[8][72];
    __shared__ uint32_t sBh[8][136], sBl[8][136];
    int tile = blockIdx.x;
    int oh = blockIdx.y;
    int b = blockIdx.z;
    int tid = threadIdx.x;
    int w = tid >> 5, lane = tid & 31;
    int g = lane >> 2, t = lane & 3;
    int wm = w >> 2, wn = w & 3;

    float o[2][4][4];
#pragma unroll
    for (int mi = 0; mi < 2; mi++)
#pragma unroll
        for (int ni = 0; ni < 4; ni++)
#pragma unroll
            for (int i = 0; i < 4; i++) o[mi][ni][i] = 0.f;

    const int KTOT = IC * 9;
    const int NCH = KTOT / KCH;

    uint32_t preAh[2], preAl[2];
    float preB[8];

    auto loadA = [&](int kc) {
#pragma unroll
        for (int i = 0; i < 2; i++) {
            int e = i * 256 + tid;
            int kk = e >> 6, oc = e & 63;
            size_t widx = (size_t)(kc / 2 + kk) * SC + oh * 64 + oc;
            preAh[i] = wh[widx];
            preAl[i] = wl[widx];
        }
    };
    auto loadB = [&](int kc) {
#pragma unroll
        for (int i = 0; i < 4; i++) {
            int e = i * 256 + tid;
            int kk = e >> 7, px = e & 127;
            int pp = tile * 128 + px;
            int r = pp >> 6, c = pp & 63;
#pragma unroll
            for (int half = 0; half < 2; half++) {
                int kg = kc + 2 * kk + half;
                int ic = kg / 9, kp = kg % 9;
                int ki = kp / 3, kj = kp % 3;
                int row = refl(stride * r + ki - 1, HI);
                int col = refl(stride * c + kj - 1, HI);
                preB[2 * i + half] = in[(((size_t)b * IC + ic) * HI + row) * HI + col];
            }
        }
    };

    loadA(0); loadB(0);
    for (int ch = 0; ch < NCH; ch++) {
        __syncthreads();
#pragma unroll
        for (int i = 0; i < 2; i++) {
            int e = i * 256 + tid;
            int kk = e >> 6, oc = e & 63;
            sAh[kk][oc] = preAh[i];
            sAl[kk][oc] = preAl[i];
        }
#pragma unroll
        for (int i = 0; i < 4; i++) {
            int e = i * 256 + tid;
            int kk = e >> 7, px = e & 127;
            float f0 = preB[2 * i], f1 = preB[2 * i + 1];
            sBh[kk][px] = packbf(f0, f1);
            sBl[kk][px] = packbf(f0 - bfhi(f0), f1 - bfhi(f1));
        }
        __syncthreads();
        if (ch + 1 < NCH) { loadA((ch + 1) * KCH); loadB((ch + 1) * KCH); }
        {
            uint32_t ah[2][4], al[2][4];
#pragma unroll
            for (int mi = 0; mi < 2; mi++) {
                int oc = wm * 32 + mi * 16;
                ah[mi][0] = sAh[t][oc + g];
                ah[mi][1] = sAh[t][oc + g + 8];
                ah[mi][2] = sAh[t + 4][oc + g];
                ah[mi][3] = sAh[t + 4][oc + g + 8];
                al[mi][0] = sAl[t][oc + g];
                al[mi][1] = sAl[t][oc + g + 8];
                al[mi][2] = sAl[t + 4][oc + g];
                al[mi][3] = sAl[t + 4][oc + g + 8];
            }
#pragma unroll
            for (int ni = 0; ni < 4; ni++) {
                int px = wn * 32 + ni * 8;
                uint32_t bh0 = sBh[t][px + g];
                uint32_t bh1 = sBh[t + 4][px + g];
                uint32_t bl0 = sBl[t][px + g];
                uint32_t bl1 = sBl[t + 4][px + g];
#pragma unroll
                for (int mi = 0; mi < 2; mi++) {
                    mma_bf16(o[mi][ni][0], o[mi][ni][1], o[mi][ni][2], o[mi][ni][3],
                             ah[mi][0], ah[mi][1], ah[mi][2], ah[mi][3], bh0, bh1);
                    mma_bf16(o[mi][ni][0], o[mi][ni][1], o[mi][ni][2], o[mi][ni][3],
                             ah[mi][0], ah[mi][1], ah[mi][2], ah[mi][3], bl0, bl1);
                    mma_bf16(o[mi][ni][0], o[mi][ni][1], o[mi][ni][2], o[mi][ni][3],
                             al[mi][0], al[mi][1], al[mi][2], al[mi][3], bh0, bh1);
                }
            }
        }
    }
#pragma unroll
    for (int mi = 0; mi < 2; mi++) {
#pragma unroll
        for (int ni = 0; ni < 4; ni++) {
#pragma unroll
            for (int half = 0; half < 2; half++) {
                int oc = oh * 64 + wm * 32 + mi * 16 + g + half * 8;
                int pp = tile * 128 + wn * 32 + ni * 8 + 2 * t;
                float* obase = &outp[((size_t)b * SC + oc) * NQ];
                obase[pp]     = o[mi][ni][half * 2];
                obase[pp + 1] = o[mi][ni][half * 2 + 1];
            }
        }
    }
}

// ---------------- conv: upsample2 + 3x3 s1 via bf16x3 mma (pipelined) ----------
__global__ __launch_bounds__(256) void conv_up_mma_kernel(const float* __restrict__ ext_in,
                                                          const float* __restrict__ w2,
                                                          int IC, int srcSel) {
    __shared__ uint32_t sAh[8][136], sAl[8][136];
    __shared__ uint32_t sBh[8][136], sBl[8][136];
    const float* in = (srcSel == 0) ? ext_in : g_att;
    int tile = blockIdx.x;
    int v = blockIdx.y;
    int rp = v >> 1, cv = v & 1;
    int b = blockIdx.z;
    int tid = threadIdx.x;
    int w = tid >> 5, lane = tid & 31;
    int g = lane >> 2, t = lane & 3;
    int wm = w >> 2, wn = w & 3;

    float o[4][4][4];
#pragma unroll
    for (int mi = 0; mi < 4; mi++)
#pragma unroll
        for (int ni = 0; ni < 4; ni++)
#pragma unroll
            for (int i = 0; i < 4; i++) o[mi][ni][i] = 0.f;

    const int KTOT = IC * 4;
    const int NCH = KTOT / KCH;

    float preA[8], preB[8];
    auto loadA = [&](int kc) {
#pragma unroll
        for (int i = 0; i < 4; i++) {
            int e = i * 256 + tid;
            int kk = e >> 7, oc = e & 127;
#pragma unroll
            for (int half = 0; half < 2; half++) {
                int kg = kc + 2 * kk + half;
                int ic = kg >> 2, pos = kg & 3;
                preA[2 * i + half] = w2[(((size_t)ic * 4 + v) * 4 + pos) * SC + oc];
            }
        }
    };
    auto loadB = [&](int kc) {
#pragma unroll
        for (int i = 0; i < 4; i++) {
            int e = i * 256 + tid;
            int kk = e >> 7, px = e & 127;
            int pp = tile * 128 + px;
            int r = pp >> 6, c = pp & 63;
#pragma unroll
            for (int half = 0; half < 2; half++) {
                int kg = kc + 2 * kk + half;
                int ic = kg >> 2, pos = kg & 3;
                int dr = pos >> 1, dc = pos & 1;
                int row = rp ? (dr ? min(r + 1, 63) : r) : (dr ? r : max(r - 1, 0));
                int col = cv ? (dc ? min(c + 1, 63) : c) : (dc ? c : max(c - 1, 0));
                preB[2 * i + half] = in[(((size_t)b * IC + ic) * 64 + row) * 64 + col];
            }
        }
    };

    loadA(0); loadB(0);
    for (int ch = 0; ch < NCH; ch++) {
        __syncthreads();
#pragma unroll
        for (int i = 0; i < 4; i++) {
            int e = i * 256 + tid;
            int kk = e >> 7, idx = e & 127;
            float a0 = preA[2 * i], a1 = preA[2 * i + 1];
            sAh[kk][idx] = packbf(a0, a1);
            sAl[kk][idx] = packbf(a0 - bfhi(a0), a1 - bfhi(a1));
            float b0 = preB[2 * i], b1 = preB[2 * i + 1];
            sBh[kk][idx] = packbf(b0, b1);
            sBl[kk][idx] = packbf(b0 - bfhi(b0), b1 - bfhi(b1));
        }
        __syncthreads();
        if (ch + 1 < NCH) { loadA((ch + 1) * KCH); loadB((ch + 1) * KCH); }
        {
            uint32_t ah[4][4], al[4][4];
#pragma unroll
            for (int mi = 0; mi < 4; mi++) {
                int oc = wm * 64 + mi * 16;
                ah[mi][0] = sAh[t][oc + g];
                ah[mi][1] = sAh[t][oc + g + 8];
                ah[mi][2] = sAh[t + 4][oc + g];
                ah[mi][3] = sAh[t + 4][oc + g + 8];
                al[mi][0] = sAl[t][oc + g];
                al[mi][1] = sAl[t][oc + g + 8];
                al[mi][2] = sAl[t + 4][oc + g];
                al[mi][3] = sAl[t + 4][oc + g + 8];
            }
#pragma unroll
            for (int ni = 0; ni < 4; ni++) {
                int px = wn * 32 + ni * 8;
                uint32_t bh0 = sBh[t][px + g];
                uint32_t bh1 = sBh[t + 4][px + g];
                uint32_t bl0 = sBl[t][px + g];
                uint32_t bl1 = sBl[t + 4][px + g];
#pragma unroll
                for (int mi = 0; mi < 4; mi++) {
                    mma_bf16(o[mi][ni][0], o[mi][ni][1], o[mi][ni][2], o[mi][ni][3],
                             ah[mi][0], ah[mi][1], ah[mi][2], ah[mi][3], bh0, bh1);
                    mma_bf16(o[mi][ni][0], o[mi][ni][1], o[mi][ni][2], o[mi][ni][3],
                             ah[mi][0], ah[mi][1], ah[mi][2], ah[mi][3], bl0, bl1);
                    mma_bf16(o[mi][ni][0], o[mi][ni][1], o[mi][ni][2], o[mi][ni][3],
                             al[mi][0], al[mi][1], al[mi][2], al[mi][3], bh0, bh1);
                }
            }
        }
    }
#pragma unroll
    for (int mi = 0; mi < 4; mi++) {
        int oc0 = wm * 64 + mi * 16;
#pragma unroll
        for (int ni = 0; ni < 4; ni++) {
            int pxb = wn * 32 + ni * 8;
#pragma unroll
            for (int half = 0; half < 2; half++) {
                int oc = oc0 + g + half * 8;
                float* obase = &g_big[(((size_t)b * SC + oc) * 128) * 128];
                int px0 = pxb + 2 * t;
                int pp0 = tile * 128 + px0;
                int r0 = pp0 >> 6, c0 = pp0 & 63;
                obase[(2 * r0 + rp) * 128 + 2 * c0 + cv] = o[mi][ni][half * 2];
                int pp1 = pp0 + 1;
                int r1 = pp1 >> 6, c1 = pp1 & 63;
                obase[(2 * r1 + rp) * 128 + 2 * c1 + cv] = o[mi][ni][half * 2 + 1];
            }
        }
    }
}

// ---------------- per-(b,c) sum / sumsq ----------------------------------------
__global__ void chan_stats_kernel(int sel, int L) {
    const float* x = (sel == 0) ? g_big : (sel == 1) ? g_q : g_v;
    float* osum = (sel == 0) ? g_sum0 : (sel == 1) ? g_sum1 : g_sum2;
    float* osq  = (sel == 0) ? g_sq0  : (sel == 1) ? g_sq1  : g_sq2;
    int bc = blockIdx.x;
    const float* p = x + (size_t)bc * L;
    float s = 0.f, q = 0.f;
    for (int i = threadIdx.x; i < L; i += 256) { float v = p[i]; s += v; q += v * v; }
    __shared__ float ss[8], sq[8];
#pragma unroll
    for (int o = 16; o > 0; o >>= 1) {
        s += __shfl_down_sync(0xffffffffu, s, o);
        q += __shfl_down_sync(0xffffffffu, q, o);
    }
    int wi = threadIdx.x >> 5;
    if ((threadIdx.x & 31) == 0) { ss[wi] = s; sq[wi] = q; }
    __syncthreads();
    if (threadIdx.x == 0) {
        float S = 0.f, Q = 0.f;
        for (int i = 0; i < 8; i++) { S += ss[i]; Q += sq[i]; }
        osum[bc] = S; osq[bc] = Q;
    }
}

// ---------------- layer stats ---------------------------------------------------
__global__ void layer_reduce_kernel() {
    int b = blockIdx.x;
    int t = threadIdx.x;
    float s = g_sum0[b * SC + t];
    float q = g_sq0[b * SC + t];
    __shared__ float ss[4], sq[4];
#pragma unroll
    for (int o = 16; o > 0; o >>= 1) {
        s += __shfl_down_sync(0xffffffffu, s, o);
        q += __shfl_down_sync(0xffffffffu, q, o);
    }
    if ((t & 31) == 0) { ss[t >> 5] = s; sq[t >> 5] = q; }
    __syncthreads();
    if (t == 0) {
        g_lsum[b] = ss[0] + ss[1] + ss[2] + ss[3];
        g_lsq[b]  = sq[0] + sq[1] + sq[2] + sq[3];
    }
}

// ---------------- ILN apply -----------------------------------------------------
__global__ void iln_apply_kernel(const float* __restrict__ rho, const float* __restrict__ gamma,
                                 const float* __restrict__ beta, const float* __restrict__ sgate,
                                 float* __restrict__ out, int mode) {
    int idx = blockIdx.x * blockDim.x + threadIdx.x;
    int total = B * SC * NS;
    if (idx >= total) return;
    int l = idx % NS;
    int c = (idx / NS) % SC;
    int b = idx / (NS * SC);
    const float n1 = (float)NS;
    float csum = g_sum0[b * SC + c], csq = g_sq0[b * SC + c];
    float im = csum / n1;
    float iv = (csq - csum * im) / (n1 - 1.f);
    const float n2 = n1 * (float)SC;
    float lm = g_lsum[b] / n2;
    float lv = (g_lsq[b] - g_lsum[b] * lm) / (n2 - 1.f);
    float v = g_big[idx];
    float r = rho[c];
    float val = r * (v - im) * rsqrtf(iv + EPS) + (1.f - r) * (v - lm) * rsqrtf(lv + EPS);
    val = val * gamma[c] + beta[c];
    if (mode == 0) {
        float o = val / (1.f + __expf(-val));
        out[((size_t)(b * 2 * SC + SC + c)) * NS + l] = o;
    } else {
        float sig = 1.f / (1.f + __expf(-val));
        out[((size_t)(b * 2 * SC + c)) * NS + l] = sig * sgate[idx];
    }
}

// ---------------- instance norm + silu ------------------------------------------
__global__ void in_apply_kernel(int sel) {
    float* x = (sel == 1) ? g_q : g_v;
    const float* sum = (sel == 1) ? g_sum1 : g_sum2;
    const float* sq  = (sel == 1) ? g_sq1  : g_sq2;
    int idx = blockIdx.x * blockDim.x + threadIdx.x;
    int total = B * SC * NQ;
    if (idx >= total) return;
    int c = (idx / NQ) % SC;
    int b = idx / (NQ * SC);
    const float n = (float)NQ;
    float s = sum[b * SC + c], q2 = sq[b * SC + c];
    float m = s / n;
    float var = q2 / n - m * m;
    float v = (x[idx] - m) * rsqrtf(var + EPS);
    x[idx] = v / (1.f + __expf(-v));
}

// ---------------- flash attention via tf32 mma.sync ----------------------------
#define AM 128
#define AN 32
__global__ __launch_bounds__(256) void attn_mma_kernel() {
    __shared__ uint32_t sK[32][40];
    __shared__ uint32_t sV[32][40];
    __shared__ uint32_t su[8][16][40];
    float (*sO)[132] = reinterpret_cast<float(*)[132]>(&su[0][0][0]);

    int q0 = blockIdx.x * AM;
    int h = blockIdx.y, b = blockIdx.z;
    int tid = threadIdx.x;
    int w = tid >> 5, lane = tid & 31;
    int g = lane >> 2, t = lane & 3;
    const float* qbase = g_q + ((size_t)b * SC + h * DH) * NQ;
    const float* vbase = g_v + ((size_t)b * SC + h * DH) * NQ;

    const float scale = 0.17677669529663687f;
    uint32_t qf[4][4];
    {
        int r0 = q0 + w * 16 + g, r1 = r0 + 8;
#pragma unroll
        for (int kst = 0; kst < 4; kst++) {
            int c0 = kst * 8 + t, c1 = c0 + 4;
            qf[kst][0] = f2tf32(qbase[(size_t)c0 * NQ + r0] * scale);
            qf[kst][1] = f2tf32(qbase[(size_t)c0 * NQ + r1] * scale);
            qf[kst][2] = f2tf32(qbase[(size_t)c1 * NQ + r0] * scale);
            qf[kst][3] = f2tf32(qbase[(size_t)c1 * NQ + r1] * scale);
        }
    }

    float m0 = -1e30f, m1 = -1e30f, l0 = 0.f, l1 = 0.f;
    float o[4][4];
#pragma unroll
    for (int ns = 0; ns < 4; ns++)
#pragma unroll
        for (int i = 0; i < 4; i++) o[ns][i] = 0.f;

    for (int jt = 0; jt < NQ / AN; jt++) {
        int j0 = jt * AN;
        __syncthreads();
#pragma unroll
        for (int i = 0; i < 16; i++) {
            int e = i * 256 + tid;
            int arr = e >> 11;
            int rem = e & 2047;
            int c = rem >> 5, j = rem & 31;
            if (arr == 0) sK[c][j] = f2tf32(qbase[(size_t)c * NQ + j0 + j]);
            else          sV[c][j] = f2tf32(vbase[(size_t)c * NQ + j0 + j]);
        }
        __syncthreads();

        float sc[4][4];
#pragma unroll
        for (int ns = 0; ns < 4; ns++) {
            float s0 = 0.f, s1 = 0.f, s2 = 0.f, s3 = 0.f;
#pragma unroll
            for (int kst = 0; kst < 4; kst++) {
                uint32_t b0 = sK[kst * 8 + t][ns * 8 + g];
                uint32_t b1 = sK[kst * 8 + t + 4][ns * 8 + g];
                mma_tf32(s0, s1, s2, s3, qf[kst][0], qf[kst][1], qf[kst][2], qf[kst][3], b0, b1);
            }
            sc[ns][0] = s0; sc[ns][1] = s1; sc[ns][2] = s2; sc[ns][3] = s3;
        }

        float mg = -1e30f, mh = -1e30f;
#pragma unroll
        for (int ns = 0; ns < 4; ns++) {
            mg = fmaxf(mg, fmaxf(sc[ns][0], sc[ns][1]));
            mh = fmaxf(mh, fmaxf(sc[ns][2], sc[ns][3]));
        }
        mg = fmaxf(mg, __shfl_xor_sync(0xffffffffu, mg, 1));
        mg = fmaxf(mg, __shfl_xor_sync(0xffffffffu, mg, 2));
        mh = fmaxf(mh, __shfl_xor_sync(0xffffffffu, mh, 1));
        mh = fmaxf(mh, __shfl_xor_sync(0xffffffffu, mh, 2));
        float mn0 = fmaxf(m0, mg), mn1 = fmaxf(m1, mh);
        float corr0 = __expf(m0 - mn0), corr1 = __expf(m1 - mn1);
        m0 = mn0; m1 = mn1;

        float rs0 = 0.f, rs1 = 0.f;
        uint32_t (*sPw)[40] = su[w];
#pragma unroll
        for (int ns = 0; ns < 4; ns++) {
            float p0 = __expf(sc[ns][0] - m0);
            float p1 = __expf(sc[ns][1] - m0);
            float p2 = __expf(sc[ns][2] - m1);
            float p3 = __expf(sc[ns][3] - m1);
            rs0 += p0 + p1; rs1 += p2 + p3;
            sPw[g][ns * 8 + 2 * t]         = f2tf32(p0);
            sPw[g][ns * 8 + 2 * t + 1]     = f2tf32(p1);
            sPw[g + 8][ns * 8 + 2 * t]     = f2tf32(p2);
            sPw[g + 8][ns * 8 + 2 * t + 1] = f2tf32(p3);
        }
        rs0 += __shfl_xor_sync(0xffffffffu, rs0, 1);
        rs0 += __shfl_xor_sync(0xffffffffu, rs0, 2);
        rs1 += __shfl_xor_sync(0xffffffffu, rs1, 1);
        rs1 += __shfl_xor_sync(0xffffffffu, rs1, 2);
        l0 = l0 * corr0 + rs0;
        l1 = l1 * corr1 + rs1;
#pragma unroll
        for (int ns = 0; ns < 4; ns++) {
            o[ns][0] *= corr0; o[ns][1] *= corr0;
            o[ns][2] *= corr1; o[ns][3] *= corr1;
        }
        __syncwarp();

        uint32_t pf[4][4];
#pragma unroll
        for (int kst = 0; kst < 4; kst++) {
            pf[kst][0] = sPw[g][kst * 8 + t];
            pf[kst][1] = sPw[g + 8][kst * 8 + t];
            pf[kst][2] = sPw[g][kst * 8 + t + 4];
            pf[kst][3] = sPw[g + 8][kst * 8 + t + 4];
        }
#pragma unroll
        for (int ns = 0; ns < 4; ns++) {
#pragma unroll
            for (int kst = 0; kst < 4; kst++) {
                uint32_t b0 = sV[ns * 8 + g][kst * 8 + t];
                uint32_t b1 = sV[ns * 8 + g][kst * 8 + t + 4];
                mma_tf32(o[ns][0], o[ns][1], o[ns][2], o[ns][3],
                         pf[kst][0], pf[kst][1], pf[kst][2], pf[kst][3], b0, b1);
            }
        }
        __syncwarp();
    }

    __syncthreads();
    float inv0 = 1.f / l0, inv1 = 1.f / l1;
#pragma unroll
    for (int ns = 0; ns < 4; ns++) {
        sO[ns * 8 + 2 * t][w * 16 + g]         = o[ns][0] * inv0;
        sO[ns * 8 + 2 * t + 1][w * 16 + g]     = o[ns][1] * inv0;
        sO[ns * 8 + 2 * t][w * 16 + g + 8]     = o[ns][2] * inv1;
        sO[ns * 8 + 2 * t + 1][w * 16 + g + 8] = o[ns][3] * inv1;
    }
    __syncthreads();
#pragma unroll
    for (int i = 0; i < 16; i++) {
        int e = i * 256 + tid;
        int c = e >> 7, qq = e & 127;
        g_att[((size_t)b * SC + h * DH + c) * NQ + q0 + qq] = sO[c][qq];
    }
}

// ---------------- launch -------------------------------------------------------
extern "C" void kernel_launch(void* const* d_in, const int* in_sizes, int n_in,
                              void* d_out, int out_size) {
    const float* y        = (const float*)d_in[0];
    const float* s        = (const float*)d_in[1];
    const float* w_blue_s = (const float*)d_in[2];
    const float* w_blue_y = (const float*)d_in[3];
    const float* w_purple = (const float*)d_in[4];
    const float* rho_p    = (const float*)d_in[5];
    const float* gamma_p  = (const float*)d_in[6];
    const float* beta_p   = (const float*)d_in[7];
    const float* w_green  = (const float*)d_in[8];
    const float* rho_g    = (const float*)d_in[9];
    const float* gamma_g  = (const float*)d_in[10];
    const float* beta_g   = (const float*)d_in[11];
    float* out = (float*)d_out;

    float* w2g; cudaGetSymbolAddress((void**)&w2g, g_w2g);
    float* w2p; cudaGetSymbolAddress((void**)&w2p, g_w2p);
    uint32_t* w1yh; cudaGetSymbolAddress((void**)&w1yh, g_w1yh);
    uint32_t* w1yl; cudaGetSymbolAddress((void**)&w1yl, g_w1yl);
    uint32_t* w1sh; cudaGetSymbolAddress((void**)&w1sh, g_w1sh);
    uint32_t* w1sl; cudaGetSymbolAddress((void**)&w1sl, g_w1sl);
    float* ypep; cudaGetSymbolAddress((void**)&ypep, g_ype);
    float* spep; cudaGetSymbolAddress((void**)&spep, g_spe);
    float* qp;   cudaGetSymbolAddress((void**)&qp, g_q);
    float* vp;   cudaGetSymbolAddress((void**)&vp, g_v);

    // aux stream + events created per call (no pre-main CUDA calls, no device mem,
    // deterministic; handles intentionally not destroyed — a few per harness call).
    cudaStream_t aux;
    cudaEvent_t ev_fork, ev_green;
    cudaStreamCreateWithFlags(&aux, cudaStreamNonBlocking);
    cudaEventCreateWithFlags(&ev_fork, cudaEventDisableTiming);
    cudaEventCreateWithFlags(&ev_green, cudaEventDisableTiming);

    // ---- setup on main (capture-origin) stream ----
    rate_init_kernel<<<1, 192>>>();
    w2_precompute_kernel<<<(SC * YC + 255) / 256, 256>>>(w_green, w2g, YC);

    // fork: green branch runs on aux, overlapping the q/v/attention chain
    cudaEventRecord(ev_fork, 0);
    cudaStreamWaitEvent(aux, ev_fork, 0);

    // ---- green branch (aux stream) ----
    conv_up_mma_kernel<<<dim3(32, 4, B), 256, 0, aux>>>(y, w2g, YC, 0);
    chan_stats_kernel<<<B * SC, 256, 0, aux>>>(0, NS);
    layer_reduce_kernel<<<B, 128, 0, aux>>>();
    iln_apply_kernel<<<(B * SC * NS) / 256, 256, 0, aux>>>(rho_g, gamma_g, beta_g, nullptr, out, 0);
    cudaEventRecord(ev_green, aux);

    // ---- main chain: remaining setup + q/v + attention ----
    w2_precompute_kernel<<<(SC * SC + 255) / 256, 256>>>(w_purple, w2p, SC);
    w1_repack_kernel<<<(YC * 9 / 2 * SC + 255) / 256, 256>>>(w_blue_y, w1yh, w1yl, YC);
    w1_repack_kernel<<<(SC * 9 / 2 * SC + 255) / 256, 256>>>(w_blue_s, w1sh, w1sl, SC);
    pe_kernel<<<(B * YC * NQ) / 256, 256>>>(y, 0, YC, NQ, 0);
    pe_kernel<<<(B * SC * NS) / 256, 256>>>(s, 1, SC, NS, 128);

    conv_blue_mma_kernel<<<dim3(32, 2, B), 256>>>(ypep, w1yh, w1yl, qp, YC, 1, 64);
    conv_blue_mma_kernel<<<dim3(32, 2, B), 256>>>(spep, w1sh, w1sl, vp, SC, 2, 128);
    chan_stats_kernel<<<B * SC, 256>>>(1, NQ);
    chan_stats_kernel<<<B * SC, 256>>>(2, NQ);
    in_apply_kernel<<<(B * SC * NQ) / 256, 256>>>(1);
    in_apply_kernel<<<(B * SC * NQ) / 256, 256>>>(2);

    attn_mma_kernel<<<dim3(NQ / AM, HEADS, B), 256>>>();

    // join: purple branch reuses g_big / g_sum0 after the green branch is done
    cudaStreamWaitEvent(0, ev_green, 0);

    // ---- purple branch (main stream) ----
    conv_up_mma_kernel<<<dim3(32, 4, B), 256>>>(nullptr, w2p, SC, 1);
    chan_stats_kernel<<<B * SC, 256>>>(0, NS);
    layer_reduce_kernel<<<B, 128>>>();
    iln_apply_kernel<<<(B * SC * NS) / 256, 256>>>(rho_p, gamma_p, beta_p, s, out, 1);
}

// round 14
// speedup vs baseline: 1.0416x; 1.0416x over previous
#include <cuda_runtime.h>
#include <cuda_bf16.h>
#include <math.h>
#include <stdint.h>

#define B 2
#define YC 256
#define SC 128
#define YH 64
#define NQ 4096        /* 64*64  */
#define SHW 128
#define NS 16384       /* 128*128 */
#define HEADS 4
#define DH 32
#define EPS 1e-5f

// ---------------- scratch (device globals; no allocations allowed) -------------
__device__ float g_ype[B * YC * NQ];
__device__ float g_spe[B * SC * NS];
__device__ float g_big[B * SC * NS];
__device__ float g_q[B * SC * NQ];
__device__ float g_v[B * SC * NQ];
__device__ float g_att[B * SC * NQ];
__device__ float g_sum0[B * SC], g_sq0[B * SC];
__device__ float g_sum1[B * SC], g_sq1[B * SC];
__device__ float g_sum2[B * SC], g_sq2[B * SC];
__device__ float g_lsum[B], g_lsq[B];
__device__ float g_rate[192];
__device__ float g_w2g[YC * 4 * 4 * SC];
__device__ float g_w2p[SC * 4 * 4 * SC];
__device__ uint32_t g_w1yh[YC * 9 / 2 * SC], g_w1yl[YC * 9 / 2 * SC];
__device__ uint32_t g_w1sh[SC * 9 / 2 * SC], g_w1sl[SC * 9 / 2 * SC];
// per-block stats partials: [b*SC+oc][slot], up uses 128 slots, blue uses 32
__device__ float g_ps[B * SC * 128], g_pq[B * SC * 128];

__device__ __forceinline__ int refl(int i, int n) {
    return i < 0 ? -i : (i >= n ? 2 * n - 2 - i : i);
}

// ---------------- mma helpers ---------------------------------------------------
__device__ __forceinline__ void mma_bf16(float& d0, float& d1, float& d2, float& d3,
                                         uint32_t a0, uint32_t a1, uint32_t a2, uint32_t a3,
                                         uint32_t b0, uint32_t b1) {
    asm volatile("mma.sync.aligned.m16n8k16.row.col.f32.bf16.bf16.f32 "
                 "{%0,%1,%2,%3}, {%4,%5,%6,%7}, {%8,%9}, {%0,%1,%2,%3};"
                 : "+f"(d0), "+f"(d1), "+f"(d2), "+f"(d3)
                 : "r"(a0), "r"(a1), "r"(a2), "r"(a3), "r"(b0), "r"(b1));
}
__device__ __forceinline__ void mma_tf32(float& d0, float& d1, float& d2, float& d3,
                                         uint32_t a0, uint32_t a1, uint32_t a2, uint32_t a3,
                                         uint32_t b0, uint32_t b1) {
    asm volatile("mma.sync.aligned.m16n8k8.row.col.f32.tf32.tf32.f32 "
                 "{%0,%1,%2,%3}, {%4,%5,%6,%7}, {%8,%9}, {%0,%1,%2,%3};"
                 : "+f"(d0), "+f"(d1), "+f"(d2), "+f"(d3)
                 : "r"(a0), "r"(a1), "r"(a2), "r"(a3), "r"(b0), "r"(b1));
}
__device__ __forceinline__ uint32_t f2tf32(float f) {
    uint32_t u; asm("cvt.rna.tf32.f32 %0, %1;" : "=r"(u) : "f"(f)); return u;
}
__device__ __forceinline__ uint32_t packbf(float f0, float f1) {
    __nv_bfloat162 v = __floats2bfloat162_rn(f0, f1);
    return *reinterpret_cast<uint32_t*>(&v);
}
__device__ __forceinline__ float bfhi(float f) {
    return __bfloat162float(__float2bfloat16_rn(f));
}

// ---------------- rate table ---------------------------------------------------
__global__ void rate_init_kernel() {
    int t = threadIdx.x;
    if (t < 128) {
        double d = (double)t / 128.0;
        g_rate[t] = (float)exp(-d * 9.210340371976184);
    } else if (t < 192) {
        double d = (double)(t - 128) / 64.0;
        g_rate[t] = (float)exp(-d * 9.210340371976184);
    }
}

// ---------------- positional encoding ------------------------------------------
__global__ void pe_kernel(const float* __restrict__ x, int outSel, int C, int L, int rateOff) {
    int idx = blockIdx.x * blockDim.x + threadIdx.x;
    int total = B * C * L;
    if (idx >= total) return;
    int l = idx % L;
    int c = (idx / L) % C;
    int half = C >> 1;
    int ch = c < half ? c : c - half;
    float rate = g_rate[rateOff + ch];
    float angf = (float)l * rate;
    double a = (double)angf;
    double k = floor(a * 0.15915494309189535);
    float r = (float)(a - k * 6.283185307179586);
    float pe = (c < half) ? sinf(r) : cosf(r);
    float* o = (outSel == 0) ? g_ype : g_spe;
    o[idx] = x[idx] + pe;
}

// ---------------- sub-filter weight precompute (upsample convs) ----------------
__global__ void w2_precompute_kernel(const float* __restrict__ w, float* __restrict__ w2,
                                     int IC) {
    int t = blockIdx.x * blockDim.x + threadIdx.x;
    if (t >= SC * IC) return;
    int oc = t % SC;
    int ic = t / SC;
    float wv[3][3];
#pragma unroll
    for (int ki = 0; ki < 3; ki++)
#pragma unroll
        for (int kj = 0; kj < 3; kj++)
            wv[ki][kj] = w[((size_t)(oc * IC + ic) * 3 + ki) * 3 + kj];
#pragma unroll
    for (int rp = 0; rp < 2; rp++) {
        float rw[2][3];
#pragma unroll
        for (int kj = 0; kj < 3; kj++) {
            if (rp == 0) { rw[0][kj] = wv[0][kj]; rw[1][kj] = wv[1][kj] + wv[2][kj]; }
            else         { rw[0][kj] = wv[0][kj] + wv[1][kj]; rw[1][kj] = wv[2][kj]; }
        }
#pragma unroll
        for (int cv = 0; cv < 2; cv++) {
#pragma unroll
            for (int dr = 0; dr < 2; dr++) {
                float f0, f1;
                if (cv == 0) { f0 = rw[dr][0]; f1 = rw[dr][1] + rw[dr][2]; }
                else         { f0 = rw[dr][0] + rw[dr][1]; f1 = rw[dr][2]; }
                int v = rp * 2 + cv;
                w2[(((size_t)ic * 4 + v) * 4 + dr * 2 + 0) * SC + oc] = f0;
                w2[(((size_t)ic * 4 + v) * 4 + dr * 2 + 1) * SC + oc] = f1;
            }
        }
    }
}

// ---------------- blue weight repack: packed bf16 k-pairs ----------------------
__global__ void w1_repack_kernel(const float* __restrict__ w, uint32_t* __restrict__ wh,
                                 uint32_t* __restrict__ wl, int IC) {
    int tot = IC * 9 / 2 * SC;
    int t = blockIdx.x * blockDim.x + threadIdx.x;
    if (t >= tot) return;
    int oc = t & 127;
    int kk = t >> 7;
    int k0 = 2 * kk, k1 = 2 * kk + 1;
    float f0 = w[((size_t)oc * IC + k0 / 9) * 9 + k0 % 9];
    float f1 = w[((size_t)oc * IC + k1 / 9) * 9 + k1 % 9];
    float h0 = bfhi(f0), h1 = bfhi(f1);
    wh[t] = packbf(f0, f1);
    wl[t] = packbf(f0 - h0, f1 - h1);
}

// ---------------- stats reduce: per-(b,oc) over block partials ------------------
__global__ void stats_reduce_kernel(int nslots, float* __restrict__ osum,
                                    float* __restrict__ osq) {
    int bc = blockIdx.x;
    float s = 0.f, q = 0.f;
    for (int i = threadIdx.x; i < nslots; i += 128) {
        s += g_ps[(size_t)bc * nslots + i];
        q += g_pq[(size_t)bc * nslots + i];
    }
    __shared__ float ss[4], sq2[4];
#pragma unroll
    for (int o = 16; o > 0; o >>= 1) {
        s += __shfl_down_sync(0xffffffffu, s, o);
        q += __shfl_down_sync(0xffffffffu, q, o);
    }
    if ((threadIdx.x & 31) == 0) { ss[threadIdx.x >> 5] = s; sq2[threadIdx.x >> 5] = q; }
    __syncthreads();
    if (threadIdx.x == 0) {
        osum[bc] = ss[0] + ss[1] + ss[2] + ss[3];
        osq[bc]  = sq2[0] + sq2[1] + sq2[2] + sq2[3];
    }
}

// ---------------- blue convs via bf16x3 implicit GEMM (pipelined, fused stats) -
#define KCH 16
__global__ __launch_bounds__(256) void conv_blue_mma_kernel(
    const float* __restrict__ in, const uint32_t* __restrict__ wh,
    const uint32_t* __restrict__ wl, float* __restrict__ outp,
    int IC, int stride, int HI) {
    __shared__ uint32_t sAh[8][72], sAl[8][72];
    __shared__ uint32_t sBh[8][136], sBl[8][136];
    __shared__ float sS[64][4], sQ[64][4];
    int tile = blockIdx.x;
    int oh = blockIdx.y;
    int b = blockIdx.z;
    int tid = threadIdx.x;
    int w = tid >> 5, lane = tid & 31;
    int g = lane >> 2, t = lane & 3;
    int wm = w >> 2, wn = w & 3;

    float o[2][4][4];
#pragma unroll
    for (int mi = 0; mi < 2; mi++)
#pragma unroll
        for (int ni = 0; ni < 4; ni++)
#pragma unroll
            for (int i = 0; i < 4; i++) o[mi][ni][i] = 0.f;

    const int KTOT = IC * 9;
    const int NCH = KTOT / KCH;

    uint32_t preAh[2], preAl[2];
    float preB[8];

    auto loadA = [&](int kc) {
#pragma unroll
        for (int i = 0; i < 2; i++) {
            int e = i * 256 + tid;
            int kk = e >> 6, oc = e & 63;
            size_t widx = (size_t)(kc / 2 + kk) * SC + oh * 64 + oc;
            preAh[i] = wh[widx];
            preAl[i] = wl[widx];
        }
    };
    auto loadB = [&](int kc) {
#pragma unroll
        for (int i = 0; i < 4; i++) {
            int e = i * 256 + tid;
            int kk = e >> 7, px = e & 127;
            int pp = tile * 128 + px;
            int r = pp >> 6, c = pp & 63;
#pragma unroll
            for (int half = 0; half < 2; half++) {
                int kg = kc + 2 * kk + half;
                int ic = kg / 9, kp = kg % 9;
                int ki = kp / 3, kj = kp % 3;
                int row = refl(stride * r + ki - 1, HI);
                int col = refl(stride * c + kj - 1, HI);
                preB[2 * i + half] = in[(((size_t)b * IC + ic) * HI + row) * HI + col];
            }
        }
    };

    loadA(0); loadB(0);
    for (int ch = 0; ch < NCH; ch++) {
        __syncthreads();
#pragma unroll
        for (int i = 0; i < 2; i++) {
            int e = i * 256 + tid;
            int kk = e >> 6, oc = e & 63;
            sAh[kk][oc] = preAh[i];
            sAl[kk][oc] = preAl[i];
        }
#pragma unroll
        for (int i = 0; i < 4; i++) {
            int e = i * 256 + tid;
            int kk = e >> 7, px = e & 127;
            float f0 = preB[2 * i], f1 = preB[2 * i + 1];
            sBh[kk][px] = packbf(f0, f1);
            sBl[kk][px] = packbf(f0 - bfhi(f0), f1 - bfhi(f1));
        }
        __syncthreads();
        if (ch + 1 < NCH) { loadA((ch + 1) * KCH); loadB((ch + 1) * KCH); }
        {
            uint32_t ah[2][4], al[2][4];
#pragma unroll
            for (int mi = 0; mi < 2; mi++) {
                int oc = wm * 32 + mi * 16;
                ah[mi][0] = sAh[t][oc + g];
                ah[mi][1] = sAh[t][oc + g + 8];
                ah[mi][2] = sAh[t + 4][oc + g];
                ah[mi][3] = sAh[t + 4][oc + g + 8];
                al[mi][0] = sAl[t][oc + g];
                al[mi][1] = sAl[t][oc + g + 8];
                al[mi][2] = sAl[t + 4][oc + g];
                al[mi][3] = sAl[t + 4][oc + g + 8];
            }
#pragma unroll
            for (int ni = 0; ni < 4; ni++) {
                int px = wn * 32 + ni * 8;
                uint32_t bh0 = sBh[t][px + g];
                uint32_t bh1 = sBh[t + 4][px + g];
                uint32_t bl0 = sBl[t][px + g];
                uint32_t bl1 = sBl[t + 4][px + g];
#pragma unroll
                for (int mi = 0; mi < 2; mi++) {
                    mma_bf16(o[mi][ni][0], o[mi][ni][1], o[mi][ni][2], o[mi][ni][3],
                             ah[mi][0], ah[mi][1], ah[mi][2], ah[mi][3], bh0, bh1);
                    mma_bf16(o[mi][ni][0], o[mi][ni][1], o[mi][ni][2], o[mi][ni][3],
                             ah[mi][0], ah[mi][1], ah[mi][2], ah[mi][3], bl0, bl1);
                    mma_bf16(o[mi][ni][0], o[mi][ni][1], o[mi][ni][2], o[mi][ni][3],
                             al[mi][0], al[mi][1], al[mi][2], al[mi][3], bh0, bh1);
                }
            }
        }
    }
    // ---- store + fused per-block stats ----
#pragma unroll
    for (int mi = 0; mi < 2; mi++) {
#pragma unroll
        for (int half = 0; half < 2; half++) {
            float s = 0.f, q = 0.f;
#pragma unroll
            for (int ni = 0; ni < 4; ni++) {
                float v0 = o[mi][ni][half * 2], v1 = o[mi][ni][half * 2 + 1];
                s += v0 + v1;
                q += v0 * v0 + v1 * v1;
                int oc = oh * 64 + wm * 32 + mi * 16 + g + half * 8;
                int pp = tile * 128 + wn * 32 + ni * 8 + 2 * t;
                float* obase = &outp[((size_t)b * SC + oc) * NQ];
                obase[pp]     = v0;
                obase[pp + 1] = v1;
            }
            s += __shfl_xor_sync(0xffffffffu, s, 1);
            s += __shfl_xor_sync(0xffffffffu, s, 2);
            q += __shfl_xor_sync(0xffffffffu, q, 1);
            q += __shfl_xor_sync(0xffffffffu, q, 2);
            if (t == 0) {
                int ocl = wm * 32 + mi * 16 + half * 8 + g;
                sS[ocl][wn] = s;
                sQ[ocl][wn] = q;
            }
        }
    }
    __syncthreads();
    if (tid < 64) {
        float S = sS[tid][0] + sS[tid][1] + sS[tid][2] + sS[tid][3];
        float Q = sQ[tid][0] + sQ[tid][1] + sQ[tid][2] + sQ[tid][3];
        int ocg = oh * 64 + tid;
        g_ps[((size_t)b * SC + ocg) * 32 + tile] = S;
        g_pq[((size_t)b * SC + ocg) * 32 + tile] = Q;
    }
}

// ---------------- conv: upsample2 + 3x3 s1 via bf16x3 mma (fused stats) --------
__global__ __launch_bounds__(256) void conv_up_mma_kernel(const float* __restrict__ ext_in,
                                                          const float* __restrict__ w2,
                                                          int IC, int srcSel) {
    __shared__ uint32_t sAh[8][136], sAl[8][136];
    __shared__ uint32_t sBh[8][136], sBl[8][136];
    __shared__ float sS[128][4], sQ[128][4];
    const float* in = (srcSel == 0) ? ext_in : g_att;
    int tile = blockIdx.x;
    int v = blockIdx.y;
    int rp = v >> 1, cv = v & 1;
    int b = blockIdx.z;
    int tid = threadIdx.x;
    int w = tid >> 5, lane = tid & 31;
    int g = lane >> 2, t = lane & 3;
    int wm = w >> 2, wn = w & 3;

    float o[4][4][4];
#pragma unroll
    for (int mi = 0; mi < 4; mi++)
#pragma unroll
        for (int ni = 0; ni < 4; ni++)
#pragma unroll
            for (int i = 0; i < 4; i++) o[mi][ni][i] = 0.f;

    const int KTOT = IC * 4;
    const int NCH = KTOT / KCH;

    float preA[8], preB[8];
    auto loadA = [&](int kc) {
#pragma unroll
        for (int i = 0; i < 4; i++) {
            int e = i * 256 + tid;
            int kk = e >> 7, oc = e & 127;
#pragma unroll
            for (int half = 0; half < 2; half++) {
                int kg = kc + 2 * kk + half;
                int ic = kg >> 2, pos = kg & 3;
                preA[2 * i + half] = w2[(((size_t)ic * 4 + v) * 4 + pos) * SC + oc];
            }
        }
    };
    auto loadB = [&](int kc) {
#pragma unroll
        for (int i = 0; i < 4; i++) {
            int e = i * 256 + tid;
            int kk = e >> 7, px = e & 127;
            int pp = tile * 128 + px;
            int r = pp >> 6, c = pp & 63;
#pragma unroll
            for (int half = 0; half < 2; half++) {
                int kg = kc + 2 * kk + half;
                int ic = kg >> 2, pos = kg & 3;
                int dr = pos >> 1, dc = pos & 1;
                int row = rp ? (dr ? min(r + 1, 63) : r) : (dr ? r : max(r - 1, 0));
                int col = cv ? (dc ? min(c + 1, 63) : c) : (dc ? c : max(c - 1, 0));
                preB[2 * i + half] = in[(((size_t)b * IC + ic) * 64 + row) * 64 + col];
            }
        }
    };

    loadA(0); loadB(0);
    for (int ch = 0; ch < NCH; ch++) {
        __syncthreads();
#pragma unroll
        for (int i = 0; i < 4; i++) {
            int e = i * 256 + tid;
            int kk = e >> 7, idx = e & 127;
            float a0 = preA[2 * i], a1 = preA[2 * i + 1];
            sAh[kk][idx] = packbf(a0, a1);
            sAl[kk][idx] = packbf(a0 - bfhi(a0), a1 - bfhi(a1));
            float b0 = preB[2 * i], b1 = preB[2 * i + 1];
            sBh[kk][idx] = packbf(b0, b1);
            sBl[kk][idx] = packbf(b0 - bfhi(b0), b1 - bfhi(b1));
        }
        __syncthreads();
        if (ch + 1 < NCH) { loadA((ch + 1) * KCH); loadB((ch + 1) * KCH); }
        {
            uint32_t ah[4][4], al[4][4];
#pragma unroll
            for (int mi = 0; mi < 4; mi++) {
                int oc = wm * 64 + mi * 16;
                ah[mi][0] = sAh[t][oc + g];
                ah[mi][1] = sAh[t][oc + g + 8];
                ah[mi][2] = sAh[t + 4][oc + g];
                ah[mi][3] = sAh[t + 4][oc + g + 8];
                al[mi][0] = sAl[t][oc + g];
                al[mi][1] = sAl[t][oc + g + 8];
                al[mi][2] = sAl[t + 4][oc + g];
                al[mi][3] = sAl[t + 4][oc + g + 8];
            }
#pragma unroll
            for (int ni = 0; ni < 4; ni++) {
                int px = wn * 32 + ni * 8;
                uint32_t bh0 = sBh[t][px + g];
                uint32_t bh1 = sBh[t + 4][px + g];
                uint32_t bl0 = sBl[t][px + g];
                uint32_t bl1 = sBl[t + 4][px + g];
#pragma unroll
                for (int mi = 0; mi < 4; mi++) {
                    mma_bf16(o[mi][ni][0], o[mi][ni][1], o[mi][ni][2], o[mi][ni][3],
                             ah[mi][0], ah[mi][1], ah[mi][2], ah[mi][3], bh0, bh1);
                    mma_bf16(o[mi][ni][0], o[mi][ni][1], o[mi][ni][2], o[mi][ni][3],
                             ah[mi][0], ah[mi][1], ah[mi][2], ah[mi][3], bl0, bl1);
                    mma_bf16(o[mi][ni][0], o[mi][ni][1], o[mi][ni][2], o[mi][ni][3],
                             al[mi][0], al[mi][1], al[mi][2], al[mi][3], bh0, bh1);
                }
            }
        }
    }
    // ---- store + fused per-block stats ----
#pragma unroll
    for (int mi = 0; mi < 4; mi++) {
        int oc0 = wm * 64 + mi * 16;
#pragma unroll
        for (int half = 0; half < 2; half++) {
            float s = 0.f, q = 0.f;
#pragma unroll
            for (int ni = 0; ni < 4; ni++) {
                int pxb = wn * 32 + ni * 8;
                float v0 = o[mi][ni][half * 2], v1 = o[mi][ni][half * 2 + 1];
                s += v0 + v1;
                q += v0 * v0 + v1 * v1;
                int oc = oc0 + g + half * 8;
                float* obase = &g_big[(((size_t)b * SC + oc) * 128) * 128];
                int px0 = pxb + 2 * t;
                int pp0 = tile * 128 + px0;
                int r0 = pp0 >> 6, c0 = pp0 & 63;
                obase[(2 * r0 + rp) * 128 + 2 * c0 + cv] = v0;
                int pp1 = pp0 + 1;
                int r1 = pp1 >> 6, c1 = pp1 & 63;
                obase[(2 * r1 + rp) * 128 + 2 * c1 + cv] = v1;
            }
            s += __shfl_xor_sync(0xffffffffu, s, 1);
            s += __shfl_xor_sync(0xffffffffu, s, 2);
            q += __shfl_xor_sync(0xffffffffu, q, 1);
            q += __shfl_xor_sync(0xffffffffu, q, 2);
            if (t == 0) {
                int ocl = oc0 + half * 8 + g;
                sS[ocl][wn] = s;
                sQ[ocl][wn] = q;
            }
        }
    }
    __syncthreads();
    if (tid < 128) {
        float S = sS[tid][0] + sS[tid][1] + sS[tid][2] + sS[tid][3];
        float Q = sQ[tid][0] + sQ[tid][1] + sQ[tid][2] + sQ[tid][3];
        g_ps[((size_t)b * SC + tid) * 128 + v * 32 + tile] = S;
        g_pq[((size_t)b * SC + tid) * 128 + v * 32 + tile] = Q;
    }
}

// ---------------- layer stats ---------------------------------------------------
__global__ void layer_reduce_kernel() {
    int b = blockIdx.x;
    int t = threadIdx.x;
    float s = g_sum0[b * SC + t];
    float q = g_sq0[b * SC + t];
    __shared__ float ss[4], sq[4];
#pragma unroll
    for (int o = 16; o > 0; o >>= 1) {
        s += __shfl_down_sync(0xffffffffu, s, o);
        q += __shfl_down_sync(0xffffffffu, q, o);
    }
    if ((t & 31) == 0) { ss[t >> 5] = s; sq[t >> 5] = q; }
    __syncthreads();
    if (t == 0) {
        g_lsum[b] = ss[0] + ss[1] + ss[2] + ss[3];
        g_lsq[b]  = sq[0] + sq[1] + sq[2] + sq[3];
    }
}

// ---------------- ILN apply -----------------------------------------------------
__global__ void iln_apply_kernel(const float* __restrict__ rho, const float* __restrict__ gamma,
                                 const float* __restrict__ beta, const float* __restrict__ sgate,
                                 float* __restrict__ out, int mode) {
    int idx = blockIdx.x * blockDim.x + threadIdx.x;
    int total = B * SC * NS;
    if (idx >= total) return;
    int l = idx % NS;
    int c = (idx / NS) % SC;
    int b = idx / (NS * SC);
    const float n1 = (float)NS;
    float csum = g_sum0[b * SC + c], csq = g_sq0[b * SC + c];
    float im = csum / n1;
    float iv = (csq - csum * im) / (n1 - 1.f);
    const float n2 = n1 * (float)SC;
    float lm = g_lsum[b] / n2;
    float lv = (g_lsq[b] - g_lsum[b] * lm) / (n2 - 1.f);
    float v = g_big[idx];
    float r = rho[c];
    float val = r * (v - im) * rsqrtf(iv + EPS) + (1.f - r) * (v - lm) * rsqrtf(lv + EPS);
    val = val * gamma[c] + beta[c];
    if (mode == 0) {
        float o = val / (1.f + __expf(-val));
        out[((size_t)(b * 2 * SC + SC + c)) * NS + l] = o;
    } else {
        float sig = 1.f / (1.f + __expf(-val));
        out[((size_t)(b * 2 * SC + c)) * NS + l] = sig * sgate[idx];
    }
}

// ---------------- instance norm + silu ------------------------------------------
__global__ void in_apply_kernel(int sel) {
    float* x = (sel == 1) ? g_q : g_v;
    const float* sum = (sel == 1) ? g_sum1 : g_sum2;
    const float* sq  = (sel == 1) ? g_sq1  : g_sq2;
    int idx = blockIdx.x * blockDim.x + threadIdx.x;
    int total = B * SC * NQ;
    if (idx >= total) return;
    int c = (idx / NQ) % SC;
    int b = idx / (NQ * SC);
    const float n = (float)NQ;
    float s = sum[b * SC + c], q2 = sq[b * SC + c];
    float m = s / n;
    float var = q2 / n - m * m;
    float v = (x[idx] - m) * rsqrtf(var + EPS);
    x[idx] = v / (1.f + __expf(-v));
}

// ---------------- flash attention via tf32 mma.sync ----------------------------
#define AM 128
#define AN 32
__global__ __launch_bounds__(256) void attn_mma_kernel() {
    __shared__ uint32_t sK[32][40];
    __shared__ uint32_t sV[32][40];
    __shared__ uint32_t su[8][16][40];
    float (*sO)[132] = reinterpret_cast<float(*)[132]>(&su[0][0][0]);

    int q0 = blockIdx.x * AM;
    int h = blockIdx.y, b = blockIdx.z;
    int tid = threadIdx.x;
    int w = tid >> 5, lane = tid & 31;
    int g = lane >> 2, t = lane & 3;
    const float* qbase = g_q + ((size_t)b * SC + h * DH) * NQ;
    const float* vbase = g_v + ((size_t)b * SC + h * DH) * NQ;

    const float scale = 0.17677669529663687f;
    uint32_t qf[4][4];
    {
        int r0 = q0 + w * 16 + g, r1 = r0 + 8;
#pragma unroll
        for (int kst = 0; kst < 4; kst++) {
            int c0 = kst * 8 + t, c1 = c0 + 4;
            qf[kst][0] = f2tf32(qbase[(size_t)c0 * NQ + r0] * scale);
            qf[kst][1] = f2tf32(qbase[(size_t)c0 * NQ + r1] * scale);
            qf[kst][2] = f2tf32(qbase[(size_t)c1 * NQ + r0] * scale);
            qf[kst][3] = f2tf32(qbase[(size_t)c1 * NQ + r1] * scale);
        }
    }

    float m0 = -1e30f, m1 = -1e30f, l0 = 0.f, l1 = 0.f;
    float o[4][4];
#pragma unroll
    for (int ns = 0; ns < 4; ns++)
#pragma unroll
        for (int i = 0; i < 4; i++) o[ns][i] = 0.f;

    for (int jt = 0; jt < NQ / AN; jt++) {
        int j0 = jt * AN;
        __syncthreads();
#pragma unroll
        for (int i = 0; i < 16; i++) {
            int e = i * 256 + tid;
            int arr = e >> 11;
            int rem = e & 2047;
            int c = rem >> 5, j = rem & 31;
            if (arr == 0) sK[c][j] = f2tf32(qbase[(size_t)c * NQ + j0 + j]);
            else          sV[c][j] = f2tf32(vbase[(size_t)c * NQ + j0 + j]);
        }
        __syncthreads();

        float sc[4][4];
#pragma unroll
        for (int ns = 0; ns < 4; ns++) {
            float s0 = 0.f, s1 = 0.f, s2 = 0.f, s3 = 0.f;
#pragma unroll
            for (int kst = 0; kst < 4; kst++) {
                uint32_t b0 = sK[kst * 8 + t][ns * 8 + g];
                uint32_t b1 = sK[kst * 8 + t + 4][ns * 8 + g];
                mma_tf32(s0, s1, s2, s3, qf[kst][0], qf[kst][1], qf[kst][2], qf[kst][3], b0, b1);
            }
            sc[ns][0] = s0; sc[ns][1] = s1; sc[ns][2] = s2; sc[ns][3] = s3;
        }

        float mg = -1e30f, mh = -1e30f;
#pragma unroll
        for (int ns = 0; ns < 4; ns++) {
            mg = fmaxf(mg, fmaxf(sc[ns][0], sc[ns][1]));
            mh = fmaxf(mh, fmaxf(sc[ns][2], sc[ns][3]));
        }
        mg = fmaxf(mg, __shfl_xor_sync(0xffffffffu, mg, 1));
        mg = fmaxf(mg, __shfl_xor_sync(0xffffffffu, mg, 2));
        mh = fmaxf(mh, __shfl_xor_sync(0xffffffffu, mh, 1));
        mh = fmaxf(mh, __shfl_xor_sync(0xffffffffu, mh, 2));
        float mn0 = fmaxf(m0, mg), mn1 = fmaxf(m1, mh);
        float corr0 = __expf(m0 - mn0), corr1 = __expf(m1 - mn1);
        m0 = mn0; m1 = mn1;

        float rs0 = 0.f, rs1 = 0.f;
        uint32_t (*sPw)[40] = su[w];
#pragma unroll
        for (int ns = 0; ns < 4; ns++) {
            float p0 = __expf(sc[ns][0] - m0);
            float p1 = __expf(sc[ns][1] - m0);
            float p2 = __expf(sc[ns][2] - m1);
            float p3 = __expf(sc[ns][3] - m1);
            rs0 += p0 + p1; rs1 += p2 + p3;
            sPw[g][ns * 8 + 2 * t]         = f2tf32(p0);
            sPw[g][ns * 8 + 2 * t + 1]     = f2tf32(p1);
            sPw[g + 8][ns * 8 + 2 * t]     = f2tf32(p2);
            sPw[g + 8][ns * 8 + 2 * t + 1] = f2tf32(p3);
        }
        rs0 += __shfl_xor_sync(0xffffffffu, rs0, 1);
        rs0 += __shfl_xor_sync(0xffffffffu, rs0, 2);
        rs1 += __shfl_xor_sync(0xffffffffu, rs1, 1);
        rs1 += __shfl_xor_sync(0xffffffffu, rs1, 2);
        l0 = l0 * corr0 + rs0;
        l1 = l1 * corr1 + rs1;
#pragma unroll
        for (int ns = 0; ns < 4; ns++) {
            o[ns][0] *= corr0; o[ns][1] *= corr0;
            o[ns][2] *= corr1; o[ns][3] *= corr1;
        }
        __syncwarp();

        uint32_t pf[4][4];
#pragma unroll
        for (int kst = 0; kst < 4; kst++) {
            pf[kst][0] = sPw[g][kst * 8 + t];
            pf[kst][1] = sPw[g + 8][kst * 8 + t];
            pf[kst][2] = sPw[g][kst * 8 + t + 4];
            pf[kst][3] = sPw[g + 8][kst * 8 + t + 4];
        }
#pragma unroll
        for (int ns = 0; ns < 4; ns++) {
#pragma unroll
            for (int kst = 0; kst < 4; kst++) {
                uint32_t b0 = sV[ns * 8 + g][kst * 8 + t];
                uint32_t b1 = sV[ns * 8 + g][kst * 8 + t + 4];
                mma_tf32(o[ns][0], o[ns][1], o[ns][2], o[ns][3],
                         pf[kst][0], pf[kst][1], pf[kst][2], pf[kst][3], b0, b1);
            }
        }
        __syncwarp();
    }

    __syncthreads();
    float inv0 = 1.f / l0, inv1 = 1.f / l1;
#pragma unroll
    for (int ns = 0; ns < 4; ns++) {
        sO[ns * 8 + 2 * t][w * 16 + g]         = o[ns][0] * inv0;
        sO[ns * 8 + 2 * t + 1][w * 16 + g]     = o[ns][1] * inv0;
        sO[ns * 8 + 2 * t][w * 16 + g + 8]     = o[ns][2] * inv1;
        sO[ns * 8 + 2 * t + 1][w * 16 + g + 8] = o[ns][3] * inv1;
    }
    __syncthreads();
#pragma unroll
    for (int i = 0; i < 16; i++) {
        int e = i * 256 + tid;
        int c = e >> 7, qq = e & 127;
        g_att[((size_t)b * SC + h * DH + c) * NQ + q0 + qq] = sO[c][qq];
    }
}

// ---------------- launch -------------------------------------------------------
extern "C" void kernel_launch(void* const* d_in, const int* in_sizes, int n_in,
                              void* d_out, int out_size) {
    const float* y        = (const float*)d_in[0];
    const float* s        = (const float*)d_in[1];
    const float* w_blue_s = (const float*)d_in[2];
    const float* w_blue_y = (const float*)d_in[3];
    const float* w_purple = (const float*)d_in[4];
    const float* rho_p    = (const float*)d_in[5];
    const float* gamma_p  = (const float*)d_in[6];
    const float* beta_p   = (const float*)d_in[7];
    const float* w_green  = (const float*)d_in[8];
    const float* rho_g    = (const float*)d_in[9];
    const float* gamma_g  = (const float*)d_in[10];
    const float* beta_g   = (const float*)d_in[11];
    float* out = (float*)d_out;

    float* w2g; cudaGetSymbolAddress((void**)&w2g, g_w2g);
    float* w2p; cudaGetSymbolAddress((void**)&w2p, g_w2p);
    uint32_t* w1yh; cudaGetSymbolAddress((void**)&w1yh, g_w1yh);
    uint32_t* w1yl; cudaGetSymbolAddress((void**)&w1yl, g_w1yl);
    uint32_t* w1sh; cudaGetSymbolAddress((void**)&w1sh, g_w1sh);
    uint32_t* w1sl; cudaGetSymbolAddress((void**)&w1sl, g_w1sl);
    float* ypep; cudaGetSymbolAddress((void**)&ypep, g_ype);
    float* spep; cudaGetSymbolAddress((void**)&spep, g_spe);
    float* qp;   cudaGetSymbolAddress((void**)&qp, g_q);
    float* vp;   cudaGetSymbolAddress((void**)&vp, g_v);
    float* sum0; cudaGetSymbolAddress((void**)&sum0, g_sum0);
    float* sq0;  cudaGetSymbolAddress((void**)&sq0, g_sq0);
    float* sum1; cudaGetSymbolAddress((void**)&sum1, g_sum1);
    float* sq1;  cudaGetSymbolAddress((void**)&sq1, g_sq1);
    float* sum2; cudaGetSymbolAddress((void**)&sum2, g_sum2);
    float* sq2;  cudaGetSymbolAddress((void**)&sq2, g_sq2);

    rate_init_kernel<<<1, 192>>>();
    w2_precompute_kernel<<<(SC * YC + 255) / 256, 256>>>(w_green, w2g, YC);
    w2_precompute_kernel<<<(SC * SC + 255) / 256, 256>>>(w_purple, w2p, SC);
    w1_repack_kernel<<<(YC * 9 / 2 * SC + 255) / 256, 256>>>(w_blue_y, w1yh, w1yl, YC);
    w1_repack_kernel<<<(SC * 9 / 2 * SC + 255) / 256, 256>>>(w_blue_s, w1sh, w1sl, SC);

    // green branch (launch #6 = conv_up green — visible to ncu -s 5 -c 1)
    conv_up_mma_kernel<<<dim3(32, 4, B), 256>>>(y, w2g, YC, 0);
    pe_kernel<<<(B * YC * NQ) / 256, 256>>>(y, 0, YC, NQ, 0);
    pe_kernel<<<(B * SC * NS) / 256, 256>>>(s, 1, SC, NS, 128);
    stats_reduce_kernel<<<B * SC, 128>>>(128, sum0, sq0);
    layer_reduce_kernel<<<B, 128>>>();
    iln_apply_kernel<<<(B * SC * NS) / 256, 256>>>(rho_g, gamma_g, beta_g, nullptr, out, 0);

    // q, v via bf16x3 implicit GEMM (stats fused into epilogues)
    conv_blue_mma_kernel<<<dim3(32, 2, B), 256>>>(ypep, w1yh, w1yl, qp, YC, 1, 64);
    stats_reduce_kernel<<<B * SC, 128>>>(32, sum1, sq1);
    conv_blue_mma_kernel<<<dim3(32, 2, B), 256>>>(spep, w1sh, w1sl, vp, SC, 2, 128);
    stats_reduce_kernel<<<B * SC, 128>>>(32, sum2, sq2);
    in_apply_kernel<<<(B * SC * NQ) / 256, 256>>>(1);
    in_apply_kernel<<<(B * SC * NQ) / 256, 256>>>(2);

    // attention
    attn_mma_kernel<<<dim3(NQ / AM, HEADS, B), 256>>>();

    // purple branch
    conv_up_mma_kernel<<<dim3(32, 4, B), 256>>>(nullptr, w2p, SC, 1);
    stats_reduce_kernel<<<B * SC, 128>>>(128, sum0, sq0);
    layer_reduce_kernel<<<B, 128>>>();
    iln_apply_kernel<<<(B * SC * NS) / 256, 256>>>(rho_p, gamma_p, beta_p, s, out, 1);
}

// round 16
// speedup vs baseline: 1.0601x; 1.0177x over previous
#include <cuda_runtime.h>
#include <cuda_bf16.h>
#include <math.h>
#include <stdint.h>

#define B 2
#define YC 256
#define SC 128
#define YH 64
#define NQ 4096        /* 64*64  */
#define SHW 128
#define NS 16384       /* 128*128 */
#define HEADS 4
#define DH 32
#define EPS 1e-5f

// ---------------- scratch (device globals; no allocations allowed) -------------
__device__ float g_ype[B * YC * NQ];
__device__ float g_spe[B * SC * NS];
__device__ float g_big[B * SC * NS];
__device__ float g_q[B * SC * NQ];
__device__ float g_v[B * SC * NQ];
__device__ float g_att[B * SC * NQ];
__device__ float g_sum0[B * SC], g_sq0[B * SC];
__device__ float g_sum1[B * SC], g_sq1[B * SC];
__device__ float g_sum2[B * SC], g_sq2[B * SC];
__device__ float g_lsum[B], g_lsq[B];
__device__ float g_rate[192];
__device__ float g_w2g[YC * 4 * 4 * SC];
__device__ float g_w2p[SC * 4 * 4 * SC];
__device__ uint32_t g_w1yh[YC * 9 / 2 * SC], g_w1yl[YC * 9 / 2 * SC];
__device__ uint32_t g_w1sh[SC * 9 / 2 * SC], g_w1sl[SC * 9 / 2 * SC];
// per-block stats partials: [b*SC+oc][slot], up uses 128 slots, blue uses 32
__device__ float g_ps[B * SC * 128], g_pq[B * SC * 128];

__device__ __forceinline__ int refl(int i, int n) {
    return i < 0 ? -i : (i >= n ? 2 * n - 2 - i : i);
}

// ---------------- mma helpers ---------------------------------------------------
__device__ __forceinline__ void mma_bf16(float& d0, float& d1, float& d2, float& d3,
                                         uint32_t a0, uint32_t a1, uint32_t a2, uint32_t a3,
                                         uint32_t b0, uint32_t b1) {
    asm volatile("mma.sync.aligned.m16n8k16.row.col.f32.bf16.bf16.f32 "
                 "{%0,%1,%2,%3}, {%4,%5,%6,%7}, {%8,%9}, {%0,%1,%2,%3};"
                 : "+f"(d0), "+f"(d1), "+f"(d2), "+f"(d3)
                 : "r"(a0), "r"(a1), "r"(a2), "r"(a3), "r"(b0), "r"(b1));
}
__device__ __forceinline__ void mma_tf32(float& d0, float& d1, float& d2, float& d3,
                                         uint32_t a0, uint32_t a1, uint32_t a2, uint32_t a3,
                                         uint32_t b0, uint32_t b1) {
    asm volatile("mma.sync.aligned.m16n8k8.row.col.f32.tf32.tf32.f32 "
                 "{%0,%1,%2,%3}, {%4,%5,%6,%7}, {%8,%9}, {%0,%1,%2,%3};"
                 : "+f"(d0), "+f"(d1), "+f"(d2), "+f"(d3)
                 : "r"(a0), "r"(a1), "r"(a2), "r"(a3), "r"(b0), "r"(b1));
}
__device__ __forceinline__ uint32_t f2tf32(float f) {
    uint32_t u; asm("cvt.rna.tf32.f32 %0, %1;" : "=r"(u) : "f"(f)); return u;
}
__device__ __forceinline__ uint32_t packbf(float f0, float f1) {
    __nv_bfloat162 v = __floats2bfloat162_rn(f0, f1);
    return *reinterpret_cast<uint32_t*>(&v);
}
__device__ __forceinline__ float bfhi(float f) {
    return __bfloat162float(__float2bfloat16_rn(f));
}

// ---------------- rate table ---------------------------------------------------
__global__ void rate_init_kernel() {
    int t = threadIdx.x;
    if (t < 128) {
        double d = (double)t / 128.0;
        g_rate[t] = (float)exp(-d * 9.210340371976184);
    } else if (t < 192) {
        double d = (double)(t - 128) / 64.0;
        g_rate[t] = (float)exp(-d * 9.210340371976184);
    }
}

// ---------------- positional encoding ------------------------------------------
__global__ void pe_kernel(const float* __restrict__ x, int outSel, int C, int L, int rateOff) {
    int idx = blockIdx.x * blockDim.x + threadIdx.x;
    int total = B * C * L;
    if (idx >= total) return;
    int l = idx % L;
    int c = (idx / L) % C;
    int half = C >> 1;
    int ch = c < half ? c : c - half;
    float rate = g_rate[rateOff + ch];
    float angf = (float)l * rate;
    double a = (double)angf;
    double k = floor(a * 0.15915494309189535);
    float r = (float)(a - k * 6.283185307179586);
    float pe = (c < half) ? sinf(r) : cosf(r);
    float* o = (outSel == 0) ? g_ype : g_spe;
    o[idx] = x[idx] + pe;
}

// ---------------- sub-filter weight precompute (upsample convs) ----------------
__global__ void w2_precompute_kernel(const float* __restrict__ w, float* __restrict__ w2,
                                     int IC) {
    int t = blockIdx.x * blockDim.x + threadIdx.x;
    if (t >= SC * IC) return;
    int oc = t % SC;
    int ic = t / SC;
    float wv[3][3];
#pragma unroll
    for (int ki = 0; ki < 3; ki++)
#pragma unroll
        for (int kj = 0; kj < 3; kj++)
            wv[ki][kj] = w[((size_t)(oc * IC + ic) * 3 + ki) * 3 + kj];
#pragma unroll
    for (int rp = 0; rp < 2; rp++) {
        float rw[2][3];
#pragma unroll
        for (int kj = 0; kj < 3; kj++) {
            if (rp == 0) { rw[0][kj] = wv[0][kj]; rw[1][kj] = wv[1][kj] + wv[2][kj]; }
            else         { rw[0][kj] = wv[0][kj] + wv[1][kj]; rw[1][kj] = wv[2][kj]; }
        }
#pragma unroll
        for (int cv = 0; cv < 2; cv++) {
#pragma unroll
            for (int dr = 0; dr < 2; dr++) {
                float f0, f1;
                if (cv == 0) { f0 = rw[dr][0]; f1 = rw[dr][1] + rw[dr][2]; }
                else         { f0 = rw[dr][0] + rw[dr][1]; f1 = rw[dr][2]; }
                int v = rp * 2 + cv;
                w2[(((size_t)ic * 4 + v) * 4 + dr * 2 + 0) * SC + oc] = f0;
                w2[(((size_t)ic * 4 + v) * 4 + dr * 2 + 1) * SC + oc] = f1;
            }
        }
    }
}

// ---------------- blue weight repack: packed bf16 k-pairs ----------------------
__global__ void w1_repack_kernel(const float* __restrict__ w, uint32_t* __restrict__ wh,
                                 uint32_t* __restrict__ wl, int IC) {
    int tot = IC * 9 / 2 * SC;
    int t = blockIdx.x * blockDim.x + threadIdx.x;
    if (t >= tot) return;
    int oc = t & 127;
    int kk = t >> 7;
    int k0 = 2 * kk, k1 = 2 * kk + 1;
    float f0 = w[((size_t)oc * IC + k0 / 9) * 9 + k0 % 9];
    float f1 = w[((size_t)oc * IC + k1 / 9) * 9 + k1 % 9];
    float h0 = bfhi(f0), h1 = bfhi(f1);
    wh[t] = packbf(f0, f1);
    wl[t] = packbf(f0 - h0, f1 - h1);
}

// ---------------- stats reduce: per-(b,oc) over block partials ------------------
__global__ void stats_reduce_kernel(int nslots, float* __restrict__ osum,
                                    float* __restrict__ osq) {
    int bc = blockIdx.x;
    float s = 0.f, q = 0.f;
    for (int i = threadIdx.x; i < nslots; i += 128) {
        s += g_ps[(size_t)bc * nslots + i];
        q += g_pq[(size_t)bc * nslots + i];
    }
    __shared__ float ss[4], sq2[4];
#pragma unroll
    for (int o = 16; o > 0; o >>= 1) {
        s += __shfl_down_sync(0xffffffffu, s, o);
        q += __shfl_down_sync(0xffffffffu, q, o);
    }
    if ((threadIdx.x & 31) == 0) { ss[threadIdx.x >> 5] = s; sq2[threadIdx.x >> 5] = q; }
    __syncthreads();
    if (threadIdx.x == 0) {
        osum[bc] = ss[0] + ss[1] + ss[2] + ss[3];
        osq[bc]  = sq2[0] + sq2[1] + sq2[2] + sq2[3];
    }
}

// ---------------- blue convs via bf16x3 implicit GEMM (pipelined, fused stats) -
#define KCH 16
__global__ __launch_bounds__(256) void conv_blue_mma_kernel(
    const float* __restrict__ in, const uint32_t* __restrict__ wh,
    const uint32_t* __restrict__ wl, float* __restrict__ outp,
    int IC, int stride, int HI) {
    __shared__ uint32_t sAh[8][72], sAl[8][72];
    __shared__ uint32_t sBh[8][136], sBl[8][136];
    __shared__ float sS[64][4], sQ[64][4];
    int tile = blockIdx.x;
    int oh = blockIdx.y;
    int b = blockIdx.z;
    int tid = threadIdx.x;
    int w = tid >> 5, lane = tid & 31;
    int g = lane >> 2, t = lane & 3;
    int wm = w >> 2, wn = w & 3;

    float o[2][4][4];
#pragma unroll
    for (int mi = 0; mi < 2; mi++)
#pragma unroll
        for (int ni = 0; ni < 4; ni++)
#pragma unroll
            for (int i = 0; i < 4; i++) o[mi][ni][i] = 0.f;

    const int KTOT = IC * 9;
    const int NCH = KTOT / KCH;

    uint32_t preAh[2], preAl[2];
    float preB[8];

    auto loadA = [&](int kc) {
#pragma unroll
        for (int i = 0; i < 2; i++) {
            int e = i * 256 + tid;
            int kk = e >> 6, oc = e & 63;
            size_t widx = (size_t)(kc / 2 + kk) * SC + oh * 64 + oc;
            preAh[i] = wh[widx];
            preAl[i] = wl[widx];
        }
    };
    auto loadB = [&](int kc) {
#pragma unroll
        for (int i = 0; i < 4; i++) {
            int e = i * 256 + tid;
            int kk = e >> 7, px = e & 127;
            int pp = tile * 128 + px;
            int r = pp >> 6, c = pp & 63;
#pragma unroll
            for (int half = 0; half < 2; half++) {
                int kg = kc + 2 * kk + half;
                int ic = kg / 9, kp = kg % 9;
                int ki = kp / 3, kj = kp % 3;
                int row = refl(stride * r + ki - 1, HI);
                int col = refl(stride * c + kj - 1, HI);
                preB[2 * i + half] = in[(((size_t)b * IC + ic) * HI + row) * HI + col];
            }
        }
    };

    loadA(0); loadB(0);
    for (int ch = 0; ch < NCH; ch++) {
        __syncthreads();
#pragma unroll
        for (int i = 0; i < 2; i++) {
            int e = i * 256 + tid;
            int kk = e >> 6, oc = e & 63;
            sAh[kk][oc] = preAh[i];
            sAl[kk][oc] = preAl[i];
        }
#pragma unroll
        for (int i = 0; i < 4; i++) {
            int e = i * 256 + tid;
            int kk = e >> 7, px = e & 127;
            float f0 = preB[2 * i], f1 = preB[2 * i + 1];
            sBh[kk][px] = packbf(f0, f1);
            sBl[kk][px] = packbf(f0 - bfhi(f0), f1 - bfhi(f1));
        }
        __syncthreads();
        if (ch + 1 < NCH) { loadA((ch + 1) * KCH); loadB((ch + 1) * KCH); }
        {
            uint32_t ah[2][4], al[2][4];
#pragma unroll
            for (int mi = 0; mi < 2; mi++) {
                int oc = wm * 32 + mi * 16;
                ah[mi][0] = sAh[t][oc + g];
                ah[mi][1] = sAh[t][oc + g + 8];
                ah[mi][2] = sAh[t + 4][oc + g];
                ah[mi][3] = sAh[t + 4][oc + g + 8];
                al[mi][0] = sAl[t][oc + g];
                al[mi][1] = sAl[t][oc + g + 8];
                al[mi][2] = sAl[t + 4][oc + g];
                al[mi][3] = sAl[t + 4][oc + g + 8];
            }
#pragma unroll
            for (int ni = 0; ni < 4; ni++) {
                int px = wn * 32 + ni * 8;
                uint32_t bh0 = sBh[t][px + g];
                uint32_t bh1 = sBh[t + 4][px + g];
                uint32_t bl0 = sBl[t][px + g];
                uint32_t bl1 = sBl[t + 4][px + g];
#pragma unroll
                for (int mi = 0; mi < 2; mi++) {
                    mma_bf16(o[mi][ni][0], o[mi][ni][1], o[mi][ni][2], o[mi][ni][3],
                             ah[mi][0], ah[mi][1], ah[mi][2], ah[mi][3], bh0, bh1);
                    mma_bf16(o[mi][ni][0], o[mi][ni][1], o[mi][ni][2], o[mi][ni][3],
                             ah[mi][0], ah[mi][1], ah[mi][2], ah[mi][3], bl0, bl1);
                    mma_bf16(o[mi][ni][0], o[mi][ni][1], o[mi][ni][2], o[mi][ni][3],
                             al[mi][0], al[mi][1], al[mi][2], al[mi][3], bh0, bh1);
                }
            }
        }
    }
    // ---- store + fused per-block stats ----
#pragma unroll
    for (int mi = 0; mi < 2; mi++) {
#pragma unroll
        for (int half = 0; half < 2; half++) {
            float s = 0.f, q = 0.f;
#pragma unroll
            for (int ni = 0; ni < 4; ni++) {
                float v0 = o[mi][ni][half * 2], v1 = o[mi][ni][half * 2 + 1];
                s += v0 + v1;
                q += v0 * v0 + v1 * v1;
                int oc = oh * 64 + wm * 32 + mi * 16 + g + half * 8;
                int pp = tile * 128 + wn * 32 + ni * 8 + 2 * t;
                float* obase = &outp[((size_t)b * SC + oc) * NQ];
                obase[pp]     = v0;
                obase[pp + 1] = v1;
            }
            s += __shfl_xor_sync(0xffffffffu, s, 1);
            s += __shfl_xor_sync(0xffffffffu, s, 2);
            q += __shfl_xor_sync(0xffffffffu, q, 1);
            q += __shfl_xor_sync(0xffffffffu, q, 2);
            if (t == 0) {
                int ocl = wm * 32 + mi * 16 + half * 8 + g;
                sS[ocl][wn] = s;
                sQ[ocl][wn] = q;
            }
        }
    }
    __syncthreads();
    if (tid < 64) {
        float S = sS[tid][0] + sS[tid][1] + sS[tid][2] + sS[tid][3];
        float Q = sQ[tid][0] + sQ[tid][1] + sQ[tid][2] + sQ[tid][3];
        int ocg = oh * 64 + tid;
        g_ps[((size_t)b * SC + ocg) * 32 + tile] = S;
        g_pq[((size_t)b * SC + ocg) * 32 + tile] = Q;
    }
}

// ---------------- conv: upsample2 + 3x3 s1 via bf16x3 mma (fused stats) --------
__global__ __launch_bounds__(256) void conv_up_mma_kernel(const float* __restrict__ ext_in,
                                                          const float* __restrict__ w2,
                                                          int IC, int srcSel) {
    __shared__ uint32_t sAh[8][136], sAl[8][136];
    __shared__ uint32_t sBh[8][136], sBl[8][136];
    __shared__ float sS[128][4], sQ[128][4];
    const float* in = (srcSel == 0) ? ext_in : g_att;
    int tile = blockIdx.x;
    int v = blockIdx.y;
    int rp = v >> 1, cv = v & 1;
    int b = blockIdx.z;
    int tid = threadIdx.x;
    int w = tid >> 5, lane = tid & 31;
    int g = lane >> 2, t = lane & 3;
    int wm = w >> 2, wn = w & 3;

    float o[4][4][4];
#pragma unroll
    for (int mi = 0; mi < 4; mi++)
#pragma unroll
        for (int ni = 0; ni < 4; ni++)
#pragma unroll
            for (int i = 0; i < 4; i++) o[mi][ni][i] = 0.f;

    const int KTOT = IC * 4;
    const int NCH = KTOT / KCH;

    float preA[8], preB[8];
    auto loadA = [&](int kc) {
#pragma unroll
        for (int i = 0; i < 4; i++) {
            int e = i * 256 + tid;
            int kk = e >> 7, oc = e & 127;
#pragma unroll
            for (int half = 0; half < 2; half++) {
                int kg = kc + 2 * kk + half;
                int ic = kg >> 2, pos = kg & 3;
                preA[2 * i + half] = w2[(((size_t)ic * 4 + v) * 4 + pos) * SC + oc];
            }
        }
    };
    auto loadB = [&](int kc) {
#pragma unroll
        for (int i = 0; i < 4; i++) {
            int e = i * 256 + tid;
            int kk = e >> 7, px = e & 127;
            int pp = tile * 128 + px;
            int r = pp >> 6, c = pp & 63;
#pragma unroll
            for (int half = 0; half < 2; half++) {
                int kg = kc + 2 * kk + half;
                int ic = kg >> 2, pos = kg & 3;
                int dr = pos >> 1, dc = pos & 1;
                int row = rp ? (dr ? min(r + 1, 63) : r) : (dr ? r : max(r - 1, 0));
                int col = cv ? (dc ? min(c + 1, 63) : c) : (dc ? c : max(c - 1, 0));
                preB[2 * i + half] = in[(((size_t)b * IC + ic) * 64 + row) * 64 + col];
            }
        }
    };

    loadA(0); loadB(0);
    for (int ch = 0; ch < NCH; ch++) {
        __syncthreads();
#pragma unroll
        for (int i = 0; i < 4; i++) {
            int e = i * 256 + tid;
            int kk = e >> 7, idx = e & 127;
            float a0 = preA[2 * i], a1 = preA[2 * i + 1];
            sAh[kk][idx] = packbf(a0, a1);
            sAl[kk][idx] = packbf(a0 - bfhi(a0), a1 - bfhi(a1));
            float b0 = preB[2 * i], b1 = preB[2 * i + 1];
            sBh[kk][idx] = packbf(b0, b1);
            sBl[kk][idx] = packbf(b0 - bfhi(b0), b1 - bfhi(b1));
        }
        __syncthreads();
        if (ch + 1 < NCH) { loadA((ch + 1) * KCH); loadB((ch + 1) * KCH); }
        {
            uint32_t ah[4][4], al[4][4];
#pragma unroll
            for (int mi = 0; mi < 4; mi++) {
                int oc = wm * 64 + mi * 16;
                ah[mi][0] = sAh[t][oc + g];
                ah[mi][1] = sAh[t][oc + g + 8];
                ah[mi][2] = sAh[t + 4][oc + g];
                ah[mi][3] = sAh[t + 4][oc + g + 8];
                al[mi][0] = sAl[t][oc + g];
                al[mi][1] = sAl[t][oc + g + 8];
                al[mi][2] = sAl[t + 4][oc + g];
                al[mi][3] = sAl[t + 4][oc + g + 8];
            }
#pragma unroll
            for (int ni = 0; ni < 4; ni++) {
                int px = wn * 32 + ni * 8;
                uint32_t bh0 = sBh[t][px + g];
                uint32_t bh1 = sBh[t + 4][px + g];
                uint32_t bl0 = sBl[t][px + g];
                uint32_t bl1 = sBl[t + 4][px + g];
#pragma unroll
                for (int mi = 0; mi < 4; mi++) {
                    mma_bf16(o[mi][ni][0], o[mi][ni][1], o[mi][ni][2], o[mi][ni][3],
                             ah[mi][0], ah[mi][1], ah[mi][2], ah[mi][3], bh0, bh1);
                    mma_bf16(o[mi][ni][0], o[mi][ni][1], o[mi][ni][2], o[mi][ni][3],
                             ah[mi][0], ah[mi][1], ah[mi][2], ah[mi][3], bl0, bl1);
                    mma_bf16(o[mi][ni][0], o[mi][ni][1], o[mi][ni][2], o[mi][ni][3],
                             al[mi][0], al[mi][1], al[mi][2], al[mi][3], bh0, bh1);
                }
            }
        }
    }
    // ---- store + fused per-block stats ----
#pragma unroll
    for (int mi = 0; mi < 4; mi++) {
        int oc0 = wm * 64 + mi * 16;
#pragma unroll
        for (int half = 0; half < 2; half++) {
            float s = 0.f, q = 0.f;
#pragma unroll
            for (int ni = 0; ni < 4; ni++) {
                int pxb = wn * 32 + ni * 8;
                float v0 = o[mi][ni][half * 2], v1 = o[mi][ni][half * 2 + 1];
                s += v0 + v1;
                q += v0 * v0 + v1 * v1;
                int oc = oc0 + g + half * 8;
                float* obase = &g_big[(((size_t)b * SC + oc) * 128) * 128];
                int px0 = pxb + 2 * t;
                int pp0 = tile * 128 + px0;
                int r0 = pp0 >> 6, c0 = pp0 & 63;
                obase[(2 * r0 + rp) * 128 + 2 * c0 + cv] = v0;
                int pp1 = pp0 + 1;
                int r1 = pp1 >> 6, c1 = pp1 & 63;
                obase[(2 * r1 + rp) * 128 + 2 * c1 + cv] = v1;
            }
            s += __shfl_xor_sync(0xffffffffu, s, 1);
            s += __shfl_xor_sync(0xffffffffu, s, 2);
            q += __shfl_xor_sync(0xffffffffu, q, 1);
            q += __shfl_xor_sync(0xffffffffu, q, 2);
            if (t == 0) {
                int ocl = oc0 + half * 8 + g;
                sS[ocl][wn] = s;
                sQ[ocl][wn] = q;
            }
        }
    }
    __syncthreads();
    if (tid < 128) {
        float S = sS[tid][0] + sS[tid][1] + sS[tid][2] + sS[tid][3];
        float Q = sQ[tid][0] + sQ[tid][1] + sQ[tid][2] + sQ[tid][3];
        g_ps[((size_t)b * SC + tid) * 128 + v * 32 + tile] = S;
        g_pq[((size_t)b * SC + tid) * 128 + v * 32 + tile] = Q;
    }
}

// ---------------- layer stats ---------------------------------------------------
__global__ void layer_reduce_kernel() {
    int b = blockIdx.x;
    int t = threadIdx.x;
    float s = g_sum0[b * SC + t];
    float q = g_sq0[b * SC + t];
    __shared__ float ss[4], sq[4];
#pragma unroll
    for (int o = 16; o > 0; o >>= 1) {
        s += __shfl_down_sync(0xffffffffu, s, o);
        q += __shfl_down_sync(0xffffffffu, q, o);
    }
    if ((t & 31) == 0) { ss[t >> 5] = s; sq[t >> 5] = q; }
    __syncthreads();
    if (t == 0) {
        g_lsum[b] = ss[0] + ss[1] + ss[2] + ss[3];
        g_lsq[b]  = sq[0] + sq[1] + sq[2] + sq[3];
    }
}

// ---------------- ILN apply (float4) --------------------------------------------
__global__ void iln_apply_kernel(const float* __restrict__ rho, const float* __restrict__ gamma,
                                 const float* __restrict__ beta, const float* __restrict__ sgate,
                                 float* __restrict__ out, int mode) {
    int idx = blockIdx.x * blockDim.x + threadIdx.x;
    int total4 = B * SC * NS / 4;
    if (idx >= total4) return;
    int l4 = idx % (NS / 4);
    int c = (idx / (NS / 4)) % SC;
    int b = idx / ((NS / 4) * SC);
    const float n1 = (float)NS;
    float csum = g_sum0[b * SC + c], csq = g_sq0[b * SC + c];
    float im = csum / n1;
    float iv = (csq - csum * im) / (n1 - 1.f);
    const float n2 = n1 * (float)SC;
    float lm = g_lsum[b] / n2;
    float lv = (g_lsq[b] - g_lsum[b] * lm) / (n2 - 1.f);
    float r = rho[c];
    float ri = r * rsqrtf(iv + EPS);
    float rl = (1.f - r) * rsqrtf(lv + EPS);
    float gam = gamma[c], bet = beta[c];
    float4 v4 = reinterpret_cast<const float4*>(g_big)[idx];
    float vv[4] = {v4.x, v4.y, v4.z, v4.w};
    float ov[4];
#pragma unroll
    for (int i = 0; i < 4; i++) {
        float val = ri * (vv[i] - im) + rl * (vv[i] - lm);
        val = val * gam + bet;
        if (mode == 0) ov[i] = val / (1.f + __expf(-val));
        else           ov[i] = 1.f / (1.f + __expf(-val));
    }
    if (mode == 0) {
        size_t off = ((size_t)(b * 2 * SC + SC + c)) * NS + l4 * 4;
        reinterpret_cast<float4*>(out + off)[0] = make_float4(ov[0], ov[1], ov[2], ov[3]);
    } else {
        float4 s4 = reinterpret_cast<const float4*>(sgate)[idx];
        size_t off = ((size_t)(b * 2 * SC + c)) * NS + l4 * 4;
        reinterpret_cast<float4*>(out + off)[0] =
            make_float4(ov[0] * s4.x, ov[1] * s4.y, ov[2] * s4.z, ov[3] * s4.w);
    }
}

// ---------------- instance norm + silu (float4) ---------------------------------
__global__ void in_apply_kernel(int sel) {
    float* x = (sel == 1) ? g_q : g_v;
    const float* sum = (sel == 1) ? g_sum1 : g_sum2;
    const float* sq  = (sel == 1) ? g_sq1  : g_sq2;
    int idx = blockIdx.x * blockDim.x + threadIdx.x;
    int total4 = B * SC * NQ / 4;
    if (idx >= total4) return;
    int c = (idx / (NQ / 4)) % SC;
    int b = idx / ((NQ / 4) * SC);
    const float n = (float)NQ;
    float s = sum[b * SC + c], q2 = sq[b * SC + c];
    float m = s / n;
    float var = q2 / n - m * m;
    float inv = rsqrtf(var + EPS);
    float4 v4 = reinterpret_cast<float4*>(x)[idx];
    float vv[4] = {v4.x, v4.y, v4.z, v4.w};
#pragma unroll
    for (int i = 0; i < 4; i++) {
        float v = (vv[i] - m) * inv;
        vv[i] = v / (1.f + __expf(-v));
    }
    reinterpret_cast<float4*>(x)[idx] = make_float4(vv[0], vv[1], vv[2], vv[3]);
}

// ---------------- flash attention via tf32 mma.sync (R14 single-buffer) --------
#define AM 128
#define AN 32
__global__ __launch_bounds__(256) void attn_mma_kernel() {
    __shared__ uint32_t sK[32][40];
    __shared__ uint32_t sV[32][40];
    __shared__ uint32_t su[8][16][40];
    float (*sO)[132] = reinterpret_cast<float(*)[132]>(&su[0][0][0]);

    int q0 = blockIdx.x * AM;
    int h = blockIdx.y, b = blockIdx.z;
    int tid = threadIdx.x;
    int w = tid >> 5, lane = tid & 31;
    int g = lane >> 2, t = lane & 3;
    const float* qbase = g_q + ((size_t)b * SC + h * DH) * NQ;
    const float* vbase = g_v + ((size_t)b * SC + h * DH) * NQ;

    const float scale = 0.17677669529663687f;
    uint32_t qf[4][4];
    {
        int r0 = q0 + w * 16 + g, r1 = r0 + 8;
#pragma unroll
        for (int kst = 0; kst < 4; kst++) {
            int c0 = kst * 8 + t, c1 = c0 + 4;
            qf[kst][0] = f2tf32(qbase[(size_t)c0 * NQ + r0] * scale);
            qf[kst][1] = f2tf32(qbase[(size_t)c0 * NQ + r1] * scale);
            qf[kst][2] = f2tf32(qbase[(size_t)c1 * NQ + r0] * scale);
            qf[kst][3] = f2tf32(qbase[(size_t)c1 * NQ + r1] * scale);
        }
    }

    float m0 = -1e30f, m1 = -1e30f, l0 = 0.f, l1 = 0.f;
    float o[4][4];
#pragma unroll
    for (int ns = 0; ns < 4; ns++)
#pragma unroll
        for (int i = 0; i < 4; i++) o[ns][i] = 0.f;

    for (int jt = 0; jt < NQ / AN; jt++) {
        int j0 = jt * AN;
        __syncthreads();
#pragma unroll
        for (int i = 0; i < 16; i++) {
            int e = i * 256 + tid;
            int arr = e >> 11;
            int rem = e & 2047;
            int c = rem >> 5, j = rem & 31;
            if (arr == 0) sK[c][j] = f2tf32(qbase[(size_t)c * NQ + j0 + j]);
            else          sV[c][j] = f2tf32(vbase[(size_t)c * NQ + j0 + j]);
        }
        __syncthreads();

        float sc[4][4];
#pragma unroll
        for (int ns = 0; ns < 4; ns++) {
            float s0 = 0.f, s1 = 0.f, s2 = 0.f, s3 = 0.f;
#pragma unroll
            for (int kst = 0; kst < 4; kst++) {
                uint32_t b0 = sK[kst * 8 + t][ns * 8 + g];
                uint32_t b1 = sK[kst * 8 + t + 4][ns * 8 + g];
                mma_tf32(s0, s1, s2, s3, qf[kst][0], qf[kst][1], qf[kst][2], qf[kst][3], b0, b1);
            }
            sc[ns][0] = s0; sc[ns][1] = s1; sc[ns][2] = s2; sc[ns][3] = s3;
        }

        float mg = -1e30f, mh = -1e30f;
#pragma unroll
        for (int ns = 0; ns < 4; ns++) {
            mg = fmaxf(mg, fmaxf(sc[ns][0], sc[ns][1]));
            mh = fmaxf(mh, fmaxf(sc[ns][2], sc[ns][3]));
        }
        mg = fmaxf(mg, __shfl_xor_sync(0xffffffffu, mg, 1));
        mg = fmaxf(mg, __shfl_xor_sync(0xffffffffu, mg, 2));
        mh = fmaxf(mh, __shfl_xor_sync(0xffffffffu, mh, 1));
        mh = fmaxf(mh, __shfl_xor_sync(0xffffffffu, mh, 2));
        float mn0 = fmaxf(m0, mg), mn1 = fmaxf(m1, mh);
        float corr0 = __expf(m0 - mn0), corr1 = __expf(m1 - mn1);
        m0 = mn0; m1 = mn1;

        float rs0 = 0.f, rs1 = 0.f;
        uint32_t (*sPw)[40] = su[w];
#pragma unroll
        for (int ns = 0; ns < 4; ns++) {
            float p0 = __expf(sc[ns][0] - m0);
            float p1 = __expf(sc[ns][1] - m0);
            float p2 = __expf(sc[ns][2] - m1);
            float p3 = __expf(sc[ns][3] - m1);
            rs0 += p0 + p1; rs1 += p2 + p3;
            sPw[g][ns * 8 + 2 * t]         = f2tf32(p0);
            sPw[g][ns * 8 + 2 * t + 1]     = f2tf32(p1);
            sPw[g + 8][ns * 8 + 2 * t]     = f2tf32(p2);
            sPw[g + 8][ns * 8 + 2 * t + 1] = f2tf32(p3);
        }
        rs0 += __shfl_xor_sync(0xffffffffu, rs0, 1);
        rs0 += __shfl_xor_sync(0xffffffffu, rs0, 2);
        rs1 += __shfl_xor_sync(0xffffffffu, rs1, 1);
        rs1 += __shfl_xor_sync(0xffffffffu, rs1, 2);
        l0 = l0 * corr0 + rs0;
        l1 = l1 * corr1 + rs1;
#pragma unroll
        for (int ns = 0; ns < 4; ns++) {
            o[ns][0] *= corr0; o[ns][1] *= corr0;
            o[ns][2] *= corr1; o[ns][3] *= corr1;
        }
        __syncwarp();

        uint32_t pf[4][4];
#pragma unroll
        for (int kst = 0; kst < 4; kst++) {
            pf[kst][0] = sPw[g][kst * 8 + t];
            pf[kst][1] = sPw[g + 8][kst * 8 + t];
            pf[kst][2] = sPw[g][kst * 8 + t + 4];
            pf[kst][3] = sPw[g + 8][kst * 8 + t + 4];
        }
#pragma unroll
        for (int ns = 0; ns < 4; ns++) {
#pragma unroll
            for (int kst = 0; kst < 4; kst++) {
                uint32_t b0 = sV[ns * 8 + g][kst * 8 + t];
                uint32_t b1 = sV[ns * 8 + g][kst * 8 + t + 4];
                mma_tf32(o[ns][0], o[ns][1], o[ns][2], o[ns][3],
                         pf[kst][0], pf[kst][1], pf[kst][2], pf[kst][3], b0, b1);
            }
        }
        __syncwarp();
    }

    __syncthreads();
    float inv0 = 1.f / l0, inv1 = 1.f / l1;
#pragma unroll
    for (int ns = 0; ns < 4; ns++) {
        sO[ns * 8 + 2 * t][w * 16 + g]         = o[ns][0] * inv0;
        sO[ns * 8 + 2 * t + 1][w * 16 + g]     = o[ns][1] * inv0;
        sO[ns * 8 + 2 * t][w * 16 + g + 8]     = o[ns][2] * inv1;
        sO[ns * 8 + 2 * t + 1][w * 16 + g + 8] = o[ns][3] * inv1;
    }
    __syncthreads();
#pragma unroll
    for (int i = 0; i < 16; i++) {
        int e = i * 256 + tid;
        int c = e >> 7, qq = e & 127;
        g_att[((size_t)b * SC + h * DH + c) * NQ + q0 + qq] = sO[c][qq];
    }
}

// ---------------- launch -------------------------------------------------------
extern "C" void kernel_launch(void* const* d_in, const int* in_sizes, int n_in,
                              void* d_out, int out_size) {
    const float* y        = (const float*)d_in[0];
    const float* s        = (const float*)d_in[1];
    const float* w_blue_s = (const float*)d_in[2];
    const float* w_blue_y = (const float*)d_in[3];
    const float* w_purple = (const float*)d_in[4];
    const float* rho_p    = (const float*)d_in[5];
    const float* gamma_p  = (const float*)d_in[6];
    const float* beta_p   = (const float*)d_in[7];
    const float* w_green  = (const float*)d_in[8];
    const float* rho_g    = (const float*)d_in[9];
    const float* gamma_g  = (const float*)d_in[10];
    const float* beta_g   = (const float*)d_in[11];
    float* out = (float*)d_out;

    float* w2g; cudaGetSymbolAddress((void**)&w2g, g_w2g);
    float* w2p; cudaGetSymbolAddress((void**)&w2p, g_w2p);
    uint32_t* w1yh; cudaGetSymbolAddress((void**)&w1yh, g_w1yh);
    uint32_t* w1yl; cudaGetSymbolAddress((void**)&w1yl, g_w1yl);
    uint32_t* w1sh; cudaGetSymbolAddress((void**)&w1sh, g_w1sh);
    uint32_t* w1sl; cudaGetSymbolAddress((void**)&w1sl, g_w1sl);
    float* ypep; cudaGetSymbolAddress((void**)&ypep, g_ype);
    float* spep; cudaGetSymbolAddress((void**)&spep, g_spe);
    float* qp;   cudaGetSymbolAddress((void**)&qp, g_q);
    float* vp;   cudaGetSymbolAddress((void**)&vp, g_v);
    float* sum0; cudaGetSymbolAddress((void**)&sum0, g_sum0);
    float* sq0;  cudaGetSymbolAddress((void**)&sq0, g_sq0);
    float* sum1; cudaGetSymbolAddress((void**)&sum1, g_sum1);
    float* sq1;  cudaGetSymbolAddress((void**)&sq1, g_sq1);
    float* sum2; cudaGetSymbolAddress((void**)&sum2, g_sum2);
    float* sq2;  cudaGetSymbolAddress((void**)&sq2, g_sq2);

    rate_init_kernel<<<1, 192>>>();
    w2_precompute_kernel<<<(SC * YC + 255) / 256, 256>>>(w_green, w2g, YC);
    w2_precompute_kernel<<<(SC * SC + 255) / 256, 256>>>(w_purple, w2p, SC);
    w1_repack_kernel<<<(YC * 9 / 2 * SC + 255) / 256, 256>>>(w_blue_y, w1yh, w1yl, YC);
    w1_repack_kernel<<<(SC * 9 / 2 * SC + 255) / 256, 256>>>(w_blue_s, w1sh, w1sl, SC);

    // green branch
    conv_up_mma_kernel<<<dim3(32, 4, B), 256>>>(y, w2g, YC, 0);
    pe_kernel<<<(B * YC * NQ) / 256, 256>>>(y, 0, YC, NQ, 0);
    pe_kernel<<<(B * SC * NS) / 256, 256>>>(s, 1, SC, NS, 128);
    stats_reduce_kernel<<<B * SC, 128>>>(128, sum0, sq0);
    layer_reduce_kernel<<<B, 128>>>();
    iln_apply_kernel<<<(B * SC * NS / 4) / 256, 256>>>(rho_g, gamma_g, beta_g, nullptr, out, 0);

    // q, v via bf16x3 implicit GEMM (stats fused into epilogues)
    conv_blue_mma_kernel<<<dim3(32, 2, B), 256>>>(ypep, w1yh, w1yl, qp, YC, 1, 64);
    stats_reduce_kernel<<<B * SC, 128>>>(32, sum1, sq1);
    conv_blue_mma_kernel<<<dim3(32, 2, B), 256>>>(spep, w1sh, w1sl, vp, SC, 2, 128);
    stats_reduce_kernel<<<B * SC, 128>>>(32, sum2, sq2);
    in_apply_kernel<<<(B * SC * NQ / 4) / 256, 256>>>(1);
    in_apply_kernel<<<(B * SC * NQ / 4) / 256, 256>>>(2);

    // attention
    attn_mma_kernel<<<dim3(NQ / AM, HEADS, B), 256>>>();

    // purple branch
    conv_up_mma_kernel<<<dim3(32, 4, B), 256>>>(nullptr, w2p, SC, 1);
    stats_reduce_kernel<<<B * SC, 128>>>(128, sum0, sq0);
    layer_reduce_kernel<<<B, 128>>>();
    iln_apply_kernel<<<(B * SC * NS / 4) / 256, 256>>>(rho_p, gamma_p, beta_p, s, out, 1);
}

// round 17
// speedup vs baseline: 1.1387x; 1.0741x over previous
#include <cuda_runtime.h>
#include <cuda_bf16.h>
#include <math.h>
#include <stdint.h>

#define B 2
#define YC 256
#define SC 128
#define YH 64
#define NQ 4096        /* 64*64  */
#define SHW 128
#define NS 16384       /* 128*128 */
#define HEADS 4
#define DH 32
#define EPS 1e-5f

// ---------------- scratch (device globals; no allocations allowed) -------------
__device__ float g_ype[B * YC * NQ];
__device__ float g_spe[B * SC * NS];
__device__ float g_big[B * SC * NS];
__device__ float g_q[B * SC * NQ];
__device__ float g_v[B * SC * NQ];
__device__ float g_att[B * SC * NQ];
__device__ float g_sum0[B * SC], g_sq0[B * SC];
__device__ float g_sum1[B * SC], g_sq1[B * SC];
__device__ float g_sum2[B * SC], g_sq2[B * SC];
__device__ float g_lsum[B], g_lsq[B];
__device__ float g_rate[192];
__device__ float g_w2g[YC * 4 * 4 * SC];
__device__ float g_w2p[SC * 4 * 4 * SC];
__device__ uint32_t g_w1yh[YC * 9 / 2 * SC], g_w1yl[YC * 9 / 2 * SC];
__device__ uint32_t g_w1sh[SC * 9 / 2 * SC], g_w1sl[SC * 9 / 2 * SC];
// per-block stats partials: [b*SC+oc][slot], up uses 128 slots, blue uses 32
__device__ float g_ps[B * SC * 128], g_pq[B * SC * 128];

__device__ __forceinline__ int refl(int i, int n) {
    return i < 0 ? -i : (i >= n ? 2 * n - 2 - i : i);
}

// ---------------- mma helpers ---------------------------------------------------
__device__ __forceinline__ void mma_bf16(float& d0, float& d1, float& d2, float& d3,
                                         uint32_t a0, uint32_t a1, uint32_t a2, uint32_t a3,
                                         uint32_t b0, uint32_t b1) {
    asm volatile("mma.sync.aligned.m16n8k16.row.col.f32.bf16.bf16.f32 "
                 "{%0,%1,%2,%3}, {%4,%5,%6,%7}, {%8,%9}, {%0,%1,%2,%3};"
                 : "+f"(d0), "+f"(d1), "+f"(d2), "+f"(d3)
                 : "r"(a0), "r"(a1), "r"(a2), "r"(a3), "r"(b0), "r"(b1));
}
__device__ __forceinline__ void mma_tf32(float& d0, float& d1, float& d2, float& d3,
                                         uint32_t a0, uint32_t a1, uint32_t a2, uint32_t a3,
                                         uint32_t b0, uint32_t b1) {
    asm volatile("mma.sync.aligned.m16n8k8.row.col.f32.tf32.tf32.f32 "
                 "{%0,%1,%2,%3}, {%4,%5,%6,%7}, {%8,%9}, {%0,%1,%2,%3};"
                 : "+f"(d0), "+f"(d1), "+f"(d2), "+f"(d3)
                 : "r"(a0), "r"(a1), "r"(a2), "r"(a3), "r"(b0), "r"(b1));
}
__device__ __forceinline__ uint32_t f2tf32(float f) {
    uint32_t u; asm("cvt.rna.tf32.f32 %0, %1;" : "=r"(u) : "f"(f)); return u;
}
__device__ __forceinline__ uint32_t packbf(float f0, float f1) {
    __nv_bfloat162 v = __floats2bfloat162_rn(f0, f1);
    return *reinterpret_cast<uint32_t*>(&v);
}
__device__ __forceinline__ float bfhi(float f) {
    return __bfloat162float(__float2bfloat16_rn(f));
}

// ---------------- rate table ---------------------------------------------------
__global__ void rate_init_kernel() {
    int t = threadIdx.x;
    if (t < 128) {
        double d = (double)t / 128.0;
        g_rate[t] = (float)exp(-d * 9.210340371976184);
    } else if (t < 192) {
        double d = (double)(t - 128) / 64.0;
        g_rate[t] = (float)exp(-d * 9.210340371976184);
    }
}

// ---------------- positional encoding (float4) ----------------------------------
__global__ void pe_kernel(const float* __restrict__ x, int outSel, int C, int L, int rateOff) {
    int idx = blockIdx.x * blockDim.x + threadIdx.x;
    int total4 = B * C * L / 4;
    if (idx >= total4) return;
    int l4 = idx % (L / 4);
    int c = (idx / (L / 4)) % C;
    int half = C >> 1;
    int ch = c < half ? c : c - half;
    float rate = g_rate[rateOff + ch];
    float4 x4 = reinterpret_cast<const float4*>(x)[idx];
    float xv[4] = {x4.x, x4.y, x4.z, x4.w};
    float ov[4];
#pragma unroll
    for (int i = 0; i < 4; i++) {
        int l = l4 * 4 + i;
        float angf = (float)l * rate;
        double a = (double)angf;
        double k = floor(a * 0.15915494309189535);
        float r = (float)(a - k * 6.283185307179586);
        float pe = (c < half) ? sinf(r) : cosf(r);
        ov[i] = xv[i] + pe;
    }
    float* o = (outSel == 0) ? g_ype : g_spe;
    reinterpret_cast<float4*>(o)[idx] = make_float4(ov[0], ov[1], ov[2], ov[3]);
}

// ---------------- sub-filter weight precompute (upsample convs) ----------------
__global__ void w2_precompute_kernel(const float* __restrict__ w, float* __restrict__ w2,
                                     int IC) {
    int t = blockIdx.x * blockDim.x + threadIdx.x;
    if (t >= SC * IC) return;
    int oc = t % SC;
    int ic = t / SC;
    float wv[3][3];
#pragma unroll
    for (int ki = 0; ki < 3; ki++)
#pragma unroll
        for (int kj = 0; kj < 3; kj++)
            wv[ki][kj] = w[((size_t)(oc * IC + ic) * 3 + ki) * 3 + kj];
#pragma unroll
    for (int rp = 0; rp < 2; rp++) {
        float rw[2][3];
#pragma unroll
        for (int kj = 0; kj < 3; kj++) {
            if (rp == 0) { rw[0][kj] = wv[0][kj]; rw[1][kj] = wv[1][kj] + wv[2][kj]; }
            else         { rw[0][kj] = wv[0][kj] + wv[1][kj]; rw[1][kj] = wv[2][kj]; }
        }
#pragma unroll
        for (int cv = 0; cv < 2; cv++) {
#pragma unroll
            for (int dr = 0; dr < 2; dr++) {
                float f0, f1;
                if (cv == 0) { f0 = rw[dr][0]; f1 = rw[dr][1] + rw[dr][2]; }
                else         { f0 = rw[dr][0] + rw[dr][1]; f1 = rw[dr][2]; }
                int v = rp * 2 + cv;
                w2[(((size_t)ic * 4 + v) * 4 + dr * 2 + 0) * SC + oc] = f0;
                w2[(((size_t)ic * 4 + v) * 4 + dr * 2 + 1) * SC + oc] = f1;
            }
        }
    }
}

// ---------------- blue weight repack: packed bf16 k-pairs ----------------------
__global__ void w1_repack_kernel(const float* __restrict__ w, uint32_t* __restrict__ wh,
                                 uint32_t* __restrict__ wl, int IC) {
    int tot = IC * 9 / 2 * SC;
    int t = blockIdx.x * blockDim.x + threadIdx.x;
    if (t >= tot) return;
    int oc = t & 127;
    int kk = t >> 7;
    int k0 = 2 * kk, k1 = 2 * kk + 1;
    float f0 = w[((size_t)oc * IC + k0 / 9) * 9 + k0 % 9];
    float f1 = w[((size_t)oc * IC + k1 / 9) * 9 + k1 % 9];
    float h0 = bfhi(f0), h1 = bfhi(f1);
    wh[t] = packbf(f0, f1);
    wl[t] = packbf(f0 - h0, f1 - h1);
}

// ---------------- stats reduce: per-(b,oc) over block partials ------------------
__global__ void stats_reduce_kernel(int nslots, float* __restrict__ osum,
                                    float* __restrict__ osq) {
    int bc = blockIdx.x;
    float s = 0.f, q = 0.f;
    for (int i = threadIdx.x; i < nslots; i += 128) {
        s += g_ps[(size_t)bc * nslots + i];
        q += g_pq[(size_t)bc * nslots + i];
    }
    __shared__ float ss[4], sq2[4];
#pragma unroll
    for (int o = 16; o > 0; o >>= 1) {
        s += __shfl_down_sync(0xffffffffu, s, o);
        q += __shfl_down_sync(0xffffffffu, q, o);
    }
    if ((threadIdx.x & 31) == 0) { ss[threadIdx.x >> 5] = s; sq2[threadIdx.x >> 5] = q; }
    __syncthreads();
    if (threadIdx.x == 0) {
        osum[bc] = ss[0] + ss[1] + ss[2] + ss[3];
        osq[bc]  = sq2[0] + sq2[1] + sq2[2] + sq2[3];
    }
}

// ---------------- blue convs via bf16x3 implicit GEMM (KCH=32, fused stats) ----
#define KCHB 32
__global__ __launch_bounds__(256) void conv_blue_mma_kernel(
    const float* __restrict__ in, const uint32_t* __restrict__ wh,
    const uint32_t* __restrict__ wl, float* __restrict__ outp,
    int IC, int stride, int HI) {
    __shared__ uint32_t sAh[16][72], sAl[16][72];
    __shared__ uint32_t sBh[16][136], sBl[16][136];
    __shared__ float sS[64][4], sQ[64][4];
    int tile = blockIdx.x;
    int oh = blockIdx.y;
    int b = blockIdx.z;
    int tid = threadIdx.x;
    int w = tid >> 5, lane = tid & 31;
    int g = lane >> 2, t = lane & 3;
    int wm = w >> 2, wn = w & 3;

    float o[2][4][4];
#pragma unroll
    for (int mi = 0; mi < 2; mi++)
#pragma unroll
        for (int ni = 0; ni < 4; ni++)
#pragma unroll
            for (int i = 0; i < 4; i++) o[mi][ni][i] = 0.f;

    const int KTOT = IC * 9;
    const int NCH = KTOT / KCHB;

    uint32_t preAh[4], preAl[4];
    float preB[16];

    auto loadA = [&](int kc) {
#pragma unroll
        for (int i = 0; i < 4; i++) {
            int e = i * 256 + tid;              // 0..1023 words (16kk x 64oc)
            int kk = e >> 6, oc = e & 63;
            size_t widx = (size_t)(kc / 2 + kk) * SC + oh * 64 + oc;
            preAh[i] = wh[widx];
            preAl[i] = wl[widx];
        }
    };
    auto loadB = [&](int kc) {
#pragma unroll
        for (int i = 0; i < 8; i++) {
            int e = i * 256 + tid;              // 0..2047 words (16kk x 128px)
            int kk = e >> 7, px = e & 127;
            int pp = tile * 128 + px;
            int r = pp >> 6, c = pp & 63;
#pragma unroll
            for (int half = 0; half < 2; half++) {
                int kg = kc + 2 * kk + half;
                int ic = kg / 9, kp = kg % 9;
                int ki = kp / 3, kj = kp % 3;
                int row = refl(stride * r + ki - 1, HI);
                int col = refl(stride * c + kj - 1, HI);
                preB[2 * i + half] = in[(((size_t)b * IC + ic) * HI + row) * HI + col];
            }
        }
    };

    loadA(0); loadB(0);
    for (int ch = 0; ch < NCH; ch++) {
        __syncthreads();
#pragma unroll
        for (int i = 0; i < 4; i++) {
            int e = i * 256 + tid;
            int kk = e >> 6, oc = e & 63;
            sAh[kk][oc] = preAh[i];
            sAl[kk][oc] = preAl[i];
        }
#pragma unroll
        for (int i = 0; i < 8; i++) {
            int e = i * 256 + tid;
            int kk = e >> 7, px = e & 127;
            float f0 = preB[2 * i], f1 = preB[2 * i + 1];
            sBh[kk][px] = packbf(f0, f1);
            sBl[kk][px] = packbf(f0 - bfhi(f0), f1 - bfhi(f1));
        }
        __syncthreads();
        if (ch + 1 < NCH) { loadA((ch + 1) * KCHB); loadB((ch + 1) * KCHB); }
#pragma unroll
        for (int kst = 0; kst < 2; kst++) {
            uint32_t ah[2][4], al[2][4];
#pragma unroll
            for (int mi = 0; mi < 2; mi++) {
                int oc = wm * 32 + mi * 16;
                ah[mi][0] = sAh[kst * 8 + t][oc + g];
                ah[mi][1] = sAh[kst * 8 + t][oc + g + 8];
                ah[mi][2] = sAh[kst * 8 + t + 4][oc + g];
                ah[mi][3] = sAh[kst * 8 + t + 4][oc + g + 8];
                al[mi][0] = sAl[kst * 8 + t][oc + g];
                al[mi][1] = sAl[kst * 8 + t][oc + g + 8];
                al[mi][2] = sAl[kst * 8 + t + 4][oc + g];
                al[mi][3] = sAl[kst * 8 + t + 4][oc + g + 8];
            }
#pragma unroll
            for (int ni = 0; ni < 4; ni++) {
                int px = wn * 32 + ni * 8;
                uint32_t bh0 = sBh[kst * 8 + t][px + g];
                uint32_t bh1 = sBh[kst * 8 + t + 4][px + g];
                uint32_t bl0 = sBl[kst * 8 + t][px + g];
                uint32_t bl1 = sBl[kst * 8 + t + 4][px + g];
#pragma unroll
                for (int mi = 0; mi < 2; mi++) {
                    mma_bf16(o[mi][ni][0], o[mi][ni][1], o[mi][ni][2], o[mi][ni][3],
                             ah[mi][0], ah[mi][1], ah[mi][2], ah[mi][3], bh0, bh1);
                    mma_bf16(o[mi][ni][0], o[mi][ni][1], o[mi][ni][2], o[mi][ni][3],
                             ah[mi][0], ah[mi][1], ah[mi][2], ah[mi][3], bl0, bl1);
                    mma_bf16(o[mi][ni][0], o[mi][ni][1], o[mi][ni][2], o[mi][ni][3],
                             al[mi][0], al[mi][1], al[mi][2], al[mi][3], bh0, bh1);
                }
            }
        }
    }
    // ---- store + fused per-block stats ----
#pragma unroll
    for (int mi = 0; mi < 2; mi++) {
#pragma unroll
        for (int half = 0; half < 2; half++) {
            float s = 0.f, q = 0.f;
#pragma unroll
            for (int ni = 0; ni < 4; ni++) {
                float v0 = o[mi][ni][half * 2], v1 = o[mi][ni][half * 2 + 1];
                s += v0 + v1;
                q += v0 * v0 + v1 * v1;
                int oc = oh * 64 + wm * 32 + mi * 16 + g + half * 8;
                int pp = tile * 128 + wn * 32 + ni * 8 + 2 * t;
                float* obase = &outp[((size_t)b * SC + oc) * NQ];
                obase[pp]     = v0;
                obase[pp + 1] = v1;
            }
            s += __shfl_xor_sync(0xffffffffu, s, 1);
            s += __shfl_xor_sync(0xffffffffu, s, 2);
            q += __shfl_xor_sync(0xffffffffu, q, 1);
            q += __shfl_xor_sync(0xffffffffu, q, 2);
            if (t == 0) {
                int ocl = wm * 32 + mi * 16 + half * 8 + g;
                sS[ocl][wn] = s;
                sQ[ocl][wn] = q;
            }
        }
    }
    __syncthreads();
    if (tid < 64) {
        float S = sS[tid][0] + sS[tid][1] + sS[tid][2] + sS[tid][3];
        float Q = sQ[tid][0] + sQ[tid][1] + sQ[tid][2] + sQ[tid][3];
        int ocg = oh * 64 + tid;
        g_ps[((size_t)b * SC + ocg) * 32 + tile] = S;
        g_pq[((size_t)b * SC + ocg) * 32 + tile] = Q;
    }
}

// ---------------- conv: upsample2 + 3x3 s1 via bf16x3 mma (KCH=16, fused stats)
#define KCH 16
__global__ __launch_bounds__(256) void conv_up_mma_kernel(const float* __restrict__ ext_in,
                                                          const float* __restrict__ w2,
                                                          int IC, int srcSel) {
    __shared__ uint32_t sAh[8][136], sAl[8][136];
    __shared__ uint32_t sBh[8][136], sBl[8][136];
    __shared__ float sS[128][4], sQ[128][4];
    const float* in = (srcSel == 0) ? ext_in : g_att;
    int tile = blockIdx.x;
    int v = blockIdx.y;
    int rp = v >> 1, cv = v & 1;
    int b = blockIdx.z;
    int tid = threadIdx.x;
    int w = tid >> 5, lane = tid & 31;
    int g = lane >> 2, t = lane & 3;
    int wm = w >> 2, wn = w & 3;

    float o[4][4][4];
#pragma unroll
    for (int mi = 0; mi < 4; mi++)
#pragma unroll
        for (int ni = 0; ni < 4; ni++)
#pragma unroll
            for (int i = 0; i < 4; i++) o[mi][ni][i] = 0.f;

    const int KTOT = IC * 4;
    const int NCH = KTOT / KCH;

    float preA[8], preB[8];
    auto loadA = [&](int kc) {
#pragma unroll
        for (int i = 0; i < 4; i++) {
            int e = i * 256 + tid;
            int kk = e >> 7, oc = e & 127;
#pragma unroll
            for (int half = 0; half < 2; half++) {
                int kg = kc + 2 * kk + half;
                int ic = kg >> 2, pos = kg & 3;
                preA[2 * i + half] = w2[(((size_t)ic * 4 + v) * 4 + pos) * SC + oc];
            }
        }
    };
    auto loadB = [&](int kc) {
#pragma unroll
        for (int i = 0; i < 4; i++) {
            int e = i * 256 + tid;
            int kk = e >> 7, px = e & 127;
            int pp = tile * 128 + px;
            int r = pp >> 6, c = pp & 63;
#pragma unroll
            for (int half = 0; half < 2; half++) {
                int kg = kc + 2 * kk + half;
                int ic = kg >> 2, pos = kg & 3;
                int dr = pos >> 1, dc = pos & 1;
                int row = rp ? (dr ? min(r + 1, 63) : r) : (dr ? r : max(r - 1, 0));
                int col = cv ? (dc ? min(c + 1, 63) : c) : (dc ? c : max(c - 1, 0));
                preB[2 * i + half] = in[(((size_t)b * IC + ic) * 64 + row) * 64 + col];
            }
        }
    };

    loadA(0); loadB(0);
    for (int ch = 0; ch < NCH; ch++) {
        __syncthreads();
#pragma unroll
        for (int i = 0; i < 4; i++) {
            int e = i * 256 + tid;
            int kk = e >> 7, idx = e & 127;
            float a0 = preA[2 * i], a1 = preA[2 * i + 1];
            sAh[kk][idx] = packbf(a0, a1);
            sAl[kk][idx] = packbf(a0 - bfhi(a0), a1 - bfhi(a1));
            float b0 = preB[2 * i], b1 = preB[2 * i + 1];
            sBh[kk][idx] = packbf(b0, b1);
            sBl[kk][idx] = packbf(b0 - bfhi(b0), b1 - bfhi(b1));
        }
        __syncthreads();
        if (ch + 1 < NCH) { loadA((ch + 1) * KCH); loadB((ch + 1) * KCH); }
        {
            uint32_t ah[4][4], al[4][4];
#pragma unroll
            for (int mi = 0; mi < 4; mi++) {
                int oc = wm * 64 + mi * 16;
                ah[mi][0] = sAh[t][oc + g];
                ah[mi][1] = sAh[t][oc + g + 8];
                ah[mi][2] = sAh[t + 4][oc + g];
                ah[mi][3] = sAh[t + 4][oc + g + 8];
                al[mi][0] = sAl[t][oc + g];
                al[mi][1] = sAl[t][oc + g + 8];
                al[mi][2] = sAl[t + 4][oc + g];
                al[mi][3] = sAl[t + 4][oc + g + 8];
            }
#pragma unroll
            for (int ni = 0; ni < 4; ni++) {
                int px = wn * 32 + ni * 8;
                uint32_t bh0 = sBh[t][px + g];
                uint32_t bh1 = sBh[t + 4][px + g];
                uint32_t bl0 = sBl[t][px + g];
                uint32_t bl1 = sBl[t + 4][px + g];
#pragma unroll
                for (int mi = 0; mi < 4; mi++) {
                    mma_bf16(o[mi][ni][0], o[mi][ni][1], o[mi][ni][2], o[mi][ni][3],
                             ah[mi][0], ah[mi][1], ah[mi][2], ah[mi][3], bh0, bh1);
                    mma_bf16(o[mi][ni][0], o[mi][ni][1], o[mi][ni][2], o[mi][ni][3],
                             ah[mi][0], ah[mi][1], ah[mi][2], ah[mi][3], bl0, bl1);
                    mma_bf16(o[mi][ni][0], o[mi][ni][1], o[mi][ni][2], o[mi][ni][3],
                             al[mi][0], al[mi][1], al[mi][2], al[mi][3], bh0, bh1);
                }
            }
        }
    }
    // ---- store + fused per-block stats ----
#pragma unroll
    for (int mi = 0; mi < 4; mi++) {
        int oc0 = wm * 64 + mi * 16;
#pragma unroll
        for (int half = 0; half < 2; half++) {
            float s = 0.f, q = 0.f;
#pragma unroll
            for (int ni = 0; ni < 4; ni++) {
                int pxb = wn * 32 + ni * 8;
                float v0 = o[mi][ni][half * 2], v1 = o[mi][ni][half * 2 + 1];
                s += v0 + v1;
                q += v0 * v0 + v1 * v1;
                int oc = oc0 + g + half * 8;
                float* obase = &g_big[(((size_t)b * SC + oc) * 128) * 128];
                int px0 = pxb + 2 * t;
                int pp0 = tile * 128 + px0;
                int r0 = pp0 >> 6, c0 = pp0 & 63;
                obase[(2 * r0 + rp) * 128 + 2 * c0 + cv] = v0;
                int pp1 = pp0 + 1;
                int r1 = pp1 >> 6, c1 = pp1 & 63;
                obase[(2 * r1 + rp) * 128 + 2 * c1 + cv] = v1;
            }
            s += __shfl_xor_sync(0xffffffffu, s, 1);
            s += __shfl_xor_sync(0xffffffffu, s, 2);
            q += __shfl_xor_sync(0xffffffffu, q, 1);
            q += __shfl_xor_sync(0xffffffffu, q, 2);
            if (t == 0) {
                int ocl = oc0 + half * 8 + g;
                sS[ocl][wn] = s;
                sQ[ocl][wn] = q;
            }
        }
    }
    __syncthreads();
    if (tid < 128) {
        float S = sS[tid][0] + sS[tid][1] + sS[tid][2] + sS[tid][3];
        float Q = sQ[tid][0] + sQ[tid][1] + sQ[tid][2] + sQ[tid][3];
        g_ps[((size_t)b * SC + tid) * 128 + v * 32 + tile] = S;
        g_pq[((size_t)b * SC + tid) * 128 + v * 32 + tile] = Q;
    }
}

// ---------------- layer stats ---------------------------------------------------
__global__ void layer_reduce_kernel() {
    int b = blockIdx.x;
    int t = threadIdx.x;
    float s = g_sum0[b * SC + t];
    float q = g_sq0[b * SC + t];
    __shared__ float ss[4], sq[4];
#pragma unroll
    for (int o = 16; o > 0; o >>= 1) {
        s += __shfl_down_sync(0xffffffffu, s, o);
        q += __shfl_down_sync(0xffffffffu, q, o);
    }
    if ((t & 31) == 0) { ss[t >> 5] = s; sq[t >> 5] = q; }
    __syncthreads();
    if (t == 0) {
        g_lsum[b] = ss[0] + ss[1] + ss[2] + ss[3];
        g_lsq[b]  = sq[0] + sq[1] + sq[2] + sq[3];
    }
}

// ---------------- ILN apply (float4) --------------------------------------------
__global__ void iln_apply_kernel(const float* __restrict__ rho, const float* __restrict__ gamma,
                                 const float* __restrict__ beta, const float* __restrict__ sgate,
                                 float* __restrict__ out, int mode) {
    int idx = blockIdx.x * blockDim.x + threadIdx.x;
    int total4 = B * SC * NS / 4;
    if (idx >= total4) return;
    int l4 = idx % (NS / 4);
    int c = (idx / (NS / 4)) % SC;
    int b = idx / ((NS / 4) * SC);
    const float n1 = (float)NS;
    float csum = g_sum0[b * SC + c], csq = g_sq0[b * SC + c];
    float im = csum / n1;
    float iv = (csq - csum * im) / (n1 - 1.f);
    const float n2 = n1 * (float)SC;
    float lm = g_lsum[b] / n2;
    float lv = (g_lsq[b] - g_lsum[b] * lm) / (n2 - 1.f);
    float r = rho[c];
    float ri = r * rsqrtf(iv + EPS);
    float rl = (1.f - r) * rsqrtf(lv + EPS);
    float gam = gamma[c], bet = beta[c];
    float4 v4 = reinterpret_cast<const float4*>(g_big)[idx];
    float vv[4] = {v4.x, v4.y, v4.z, v4.w};
    float ov[4];
#pragma unroll
    for (int i = 0; i < 4; i++) {
        float val = ri * (vv[i] - im) + rl * (vv[i] - lm);
        val = val * gam + bet;
        if (mode == 0) ov[i] = val / (1.f + __expf(-val));
        else           ov[i] = 1.f / (1.f + __expf(-val));
    }
    if (mode == 0) {
        size_t off = ((size_t)(b * 2 * SC + SC + c)) * NS + l4 * 4;
        reinterpret_cast<float4*>(out + off)[0] = make_float4(ov[0], ov[1], ov[2], ov[3]);
    } else {
        float4 s4 = reinterpret_cast<const float4*>(sgate)[idx];
        size_t off = ((size_t)(b * 2 * SC + c)) * NS + l4 * 4;
        reinterpret_cast<float4*>(out + off)[0] =
            make_float4(ov[0] * s4.x, ov[1] * s4.y, ov[2] * s4.z, ov[3] * s4.w);
    }
}

// ---------------- instance norm + silu (float4) ---------------------------------
__global__ void in_apply_kernel(int sel) {
    float* x = (sel == 1) ? g_q : g_v;
    const float* sum = (sel == 1) ? g_sum1 : g_sum2;
    const float* sq  = (sel == 1) ? g_sq1  : g_sq2;
    int idx = blockIdx.x * blockDim.x + threadIdx.x;
    int total4 = B * SC * NQ / 4;
    if (idx >= total4) return;
    int c = (idx / (NQ / 4)) % SC;
    int b = idx / ((NQ / 4) * SC);
    const float n = (float)NQ;
    float s = sum[b * SC + c], q2 = sq[b * SC + c];
    float m = s / n;
    float var = q2 / n - m * m;
    float inv = rsqrtf(var + EPS);
    float4 v4 = reinterpret_cast<float4*>(x)[idx];
    float vv[4] = {v4.x, v4.y, v4.z, v4.w};
#pragma unroll
    for (int i = 0; i < 4; i++) {
        float v = (vv[i] - m) * inv;
        vv[i] = v / (1.f + __expf(-v));
    }
    reinterpret_cast<float4*>(x)[idx] = make_float4(vv[0], vv[1], vv[2], vv[3]);
}

// ---------------- flash attention via tf32 mma.sync (single-buffer) ------------
#define AM 128
#define AN 32
__global__ __launch_bounds__(256) void attn_mma_kernel() {
    __shared__ uint32_t sK[32][40];
    __shared__ uint32_t sV[32][40];
    __shared__ uint32_t su[8][16][40];
    float (*sO)[132] = reinterpret_cast<float(*)[132]>(&su[0][0][0]);

    int q0 = blockIdx.x * AM;
    int h = blockIdx.y, b = blockIdx.z;
    int tid = threadIdx.x;
    int w = tid >> 5, lane = tid & 31;
    int g = lane >> 2, t = lane & 3;
    const float* qbase = g_q + ((size_t)b * SC + h * DH) * NQ;
    const float* vbase = g_v + ((size_t)b * SC + h * DH) * NQ;

    const float scale = 0.17677669529663687f;
    uint32_t qf[4][4];
    {
        int r0 = q0 + w * 16 + g, r1 = r0 + 8;
#pragma unroll
        for (int kst = 0; kst < 4; kst++) {
            int c0 = kst * 8 + t, c1 = c0 + 4;
            qf[kst][0] = f2tf32(qbase[(size_t)c0 * NQ + r0] * scale);
            qf[kst][1] = f2tf32(qbase[(size_t)c0 * NQ + r1] * scale);
            qf[kst][2] = f2tf32(qbase[(size_t)c1 * NQ + r0] * scale);
            qf[kst][3] = f2tf32(qbase[(size_t)c1 * NQ + r1] * scale);
        }
    }

    float m0 = -1e30f, m1 = -1e30f, l0 = 0.f, l1 = 0.f;
    float o[4][4];
#pragma unroll
    for (int ns = 0; ns < 4; ns++)
#pragma unroll
        for (int i = 0; i < 4; i++) o[ns][i] = 0.f;

    for (int jt = 0; jt < NQ / AN; jt++) {
        int j0 = jt * AN;
        __syncthreads();
#pragma unroll
        for (int i = 0; i < 16; i++) {
            int e = i * 256 + tid;
            int arr = e >> 11;
            int rem = e & 2047;
            int c = rem >> 5, j = rem & 31;
            if (arr == 0) sK[c][j] = f2tf32(qbase[(size_t)c * NQ + j0 + j]);
            else          sV[c][j] = f2tf32(vbase[(size_t)c * NQ + j0 + j]);
        }
        __syncthreads();

        float sc[4][4];
#pragma unroll
        for (int ns = 0; ns < 4; ns++) {
            float s0 = 0.f, s1 = 0.f, s2 = 0.f, s3 = 0.f;
#pragma unroll
            for (int kst = 0; kst < 4; kst++) {
                uint32_t b0 = sK[kst * 8 + t][ns * 8 + g];
                uint32_t b1 = sK[kst * 8 + t + 4][ns * 8 + g];
                mma_tf32(s0, s1, s2, s3, qf[kst][0], qf[kst][1], qf[kst][2], qf[kst][3], b0, b1);
            }
            sc[ns][0] = s0; sc[ns][1] = s1; sc[ns][2] = s2; sc[ns][3] = s3;
        }

        float mg = -1e30f, mh = -1e30f;
#pragma unroll
        for (int ns = 0; ns < 4; ns++) {
            mg = fmaxf(mg, fmaxf(sc[ns][0], sc[ns][1]));
            mh = fmaxf(mh, fmaxf(sc[ns][2], sc[ns][3]));
        }
        mg = fmaxf(mg, __shfl_xor_sync(0xffffffffu, mg, 1));
        mg = fmaxf(mg, __shfl_xor_sync(0xffffffffu, mg, 2));
        mh = fmaxf(mh, __shfl_xor_sync(0xffffffffu, mh, 1));
        mh = fmaxf(mh, __shfl_xor_sync(0xffffffffu, mh, 2));
        float mn0 = fmaxf(m0, mg), mn1 = fmaxf(m1, mh);
        float corr0 = __expf(m0 - mn0), corr1 = __expf(m1 - mn1);
        m0 = mn0; m1 = mn1;

        float rs0 = 0.f, rs1 = 0.f;
        uint32_t (*sPw)[40] = su[w];
#pragma unroll
        for (int ns = 0; ns < 4; ns++) {
            float p0 = __expf(sc[ns][0] - m0);
            float p1 = __expf(sc[ns][1] - m0);
            float p2 = __expf(sc[ns][2] - m1);
            float p3 = __expf(sc[ns][3] - m1);
            rs0 += p0 + p1; rs1 += p2 + p3;
            sPw[g][ns * 8 + 2 * t]         = f2tf32(p0);
            sPw[g][ns * 8 + 2 * t + 1]     = f2tf32(p1);
            sPw[g + 8][ns * 8 + 2 * t]     = f2tf32(p2);
            sPw[g + 8][ns * 8 + 2 * t + 1] = f2tf32(p3);
        }
        rs0 += __shfl_xor_sync(0xffffffffu, rs0, 1);
        rs0 += __shfl_xor_sync(0xffffffffu, rs0, 2);
        rs1 += __shfl_xor_sync(0xffffffffu, rs1, 1);
        rs1 += __shfl_xor_sync(0xffffffffu, rs1, 2);
        l0 = l0 * corr0 + rs0;
        l1 = l1 * corr1 + rs1;
#pragma unroll
        for (int ns = 0; ns < 4; ns++) {
            o[ns][0] *= corr0; o[ns][1] *= corr0;
            o[ns][2] *= corr1; o[ns][3] *= corr1;
        }
        __syncwarp();

        uint32_t pf[4][4];
#pragma unroll
        for (int kst = 0; kst < 4; kst++) {
            pf[kst][0] = sPw[g][kst * 8 + t];
            pf[kst][1] = sPw[g + 8][kst * 8 + t];
            pf[kst][2] = sPw[g][kst * 8 + t + 4];
            pf[kst][3] = sPw[g + 8][kst * 8 + t + 4];
        }
#pragma unroll
        for (int ns = 0; ns < 4; ns++) {
#pragma unroll
            for (int kst = 0; kst < 4; kst++) {
                uint32_t b0 = sV[ns * 8 + g][kst * 8 + t];
                uint32_t b1 = sV[ns * 8 + g][kst * 8 + t + 4];
                mma_tf32(o[ns][0], o[ns][1], o[ns][2], o[ns][3],
                         pf[kst][0], pf[kst][1], pf[kst][2], pf[kst][3], b0, b1);
            }
        }
        __syncwarp();
    }

    __syncthreads();
    float inv0 = 1.f / l0, inv1 = 1.f / l1;
#pragma unroll
    for (int ns = 0; ns < 4; ns++) {
        sO[ns * 8 + 2 * t][w * 16 + g]         = o[ns][0] * inv0;
        sO[ns * 8 + 2 * t + 1][w * 16 + g]     = o[ns][1] * inv0;
        sO[ns * 8 + 2 * t][w * 16 + g + 8]     = o[ns][2] * inv1;
        sO[ns * 8 + 2 * t + 1][w * 16 + g + 8] = o[ns][3] * inv1;
    }
    __syncthreads();
#pragma unroll
    for (int i = 0; i < 16; i++) {
        int e = i * 256 + tid;
        int c = e >> 7, qq = e & 127;
        g_att[((size_t)b * SC + h * DH + c) * NQ + q0 + qq] = sO[c][qq];
    }
}

// ---------------- launch -------------------------------------------------------
extern "C" void kernel_launch(void* const* d_in, const int* in_sizes, int n_in,
                              void* d_out, int out_size) {
    const float* y        = (const float*)d_in[0];
    const float* s        = (const float*)d_in[1];
    const float* w_blue_s = (const float*)d_in[2];
    const float* w_blue_y = (const float*)d_in[3];
    const float* w_purple = (const float*)d_in[4];
    const float* rho_p    = (const float*)d_in[5];
    const float* gamma_p  = (const float*)d_in[6];
    const float* beta_p   = (const float*)d_in[7];
    const float* w_green  = (const float*)d_in[8];
    const float* rho_g    = (const float*)d_in[9];
    const float* gamma_g  = (const float*)d_in[10];
    const float* beta_g   = (const float*)d_in[11];
    float* out = (float*)d_out;

    float* w2g; cudaGetSymbolAddress((void**)&w2g, g_w2g);
    float* w2p; cudaGetSymbolAddress((void**)&w2p, g_w2p);
    uint32_t* w1yh; cudaGetSymbolAddress((void**)&w1yh, g_w1yh);
    uint32_t* w1yl; cudaGetSymbolAddress((void**)&w1yl, g_w1yl);
    uint32_t* w1sh; cudaGetSymbolAddress((void**)&w1sh, g_w1sh);
    uint32_t* w1sl; cudaGetSymbolAddress((void**)&w1sl, g_w1sl);
    float* ypep; cudaGetSymbolAddress((void**)&ypep, g_ype);
    float* spep; cudaGetSymbolAddress((void**)&spep, g_spe);
    float* qp;   cudaGetSymbolAddress((void**)&qp, g_q);
    float* vp;   cudaGetSymbolAddress((void**)&vp, g_v);
    float* sum0; cudaGetSymbolAddress((void**)&sum0, g_sum0);
    float* sq0;  cudaGetSymbolAddress((void**)&sq0, g_sq0);
    float* sum1; cudaGetSymbolAddress((void**)&sum1, g_sum1);
    float* sq1;  cudaGetSymbolAddress((void**)&sq1, g_sq1);
    float* sum2; cudaGetSymbolAddress((void**)&sum2, g_sum2);
    float* sq2;  cudaGetSymbolAddress((void**)&sq2, g_sq2);

    rate_init_kernel<<<1, 192>>>();
    w2_precompute_kernel<<<(SC * YC + 255) / 256, 256>>>(w_green, w2g, YC);
    w2_precompute_kernel<<<(SC * SC + 255) / 256, 256>>>(w_purple, w2p, SC);
    w1_repack_kernel<<<(YC * 9 / 2 * SC + 255) / 256, 256>>>(w_blue_y, w1yh, w1yl, YC);
    w1_repack_kernel<<<(SC * 9 / 2 * SC + 255) / 256, 256>>>(w_blue_s, w1sh, w1sl, SC);

    // green branch
    conv_up_mma_kernel<<<dim3(32, 4, B), 256>>>(y, w2g, YC, 0);
    pe_kernel<<<(B * YC * NQ / 4) / 256, 256>>>(y, 0, YC, NQ, 0);
    pe_kernel<<<(B * SC * NS / 4) / 256, 256>>>(s, 1, SC, NS, 128);
    stats_reduce_kernel<<<B * SC, 128>>>(128, sum0, sq0);
    layer_reduce_kernel<<<B, 128>>>();
    iln_apply_kernel<<<(B * SC * NS / 4) / 256, 256>>>(rho_g, gamma_g, beta_g, nullptr, out, 0);

    // q, v via bf16x3 implicit GEMM (stats fused into epilogues)
    conv_blue_mma_kernel<<<dim3(32, 2, B), 256>>>(ypep, w1yh, w1yl, qp, YC, 1, 64);
    stats_reduce_kernel<<<B * SC, 128>>>(32, sum1, sq1);
    conv_blue_mma_kernel<<<dim3(32, 2, B), 256>>>(spep, w1sh, w1sl, vp, SC, 2, 128);
    stats_reduce_kernel<<<B * SC, 128>>>(32, sum2, sq2);
    in_apply_kernel<<<(B * SC * NQ / 4) / 256, 256>>>(1);
    in_apply_kernel<<<(B * SC * NQ / 4) / 256, 256>>>(2);

    // attention
    attn_mma_kernel<<<dim3(NQ / AM, HEADS, B), 256>>>();

    // purple branch
    conv_up_mma_kernel<<<dim3(32, 4, B), 256>>>(nullptr, w2p, SC, 1);
    stats_reduce_kernel<<<B * SC, 128>>>(128, sum0, sq0);
    layer_reduce_kernel<<<B, 128>>>();
    iln_apply_kernel<<<(B * SC * NS / 4) / 256, 256>>>(rho_p, gamma_p, beta_p, s, out, 1);
}